// round 8
// baseline (speedup 1.0000x reference)
#include <cuda_runtime.h>
#include <cuda_bf16.h>
#include <math.h>
#include <stdint.h>

// Problem constants
#define SEQ   2048
#define DIM   4096
#define NH    32
#define NKV   8
#define HD    128
#define QKV_N 6144
#define KOFF  4096
#define VOFF  5120

// Scratch (__device__ globals)
__device__ float g_qkv[SEQ * QKV_N];
__device__ __nv_bfloat16 g_xh[SEQ * DIM],    g_xl[SEQ * DIM];
__device__ __nv_bfloat16 g_wqh[QKV_N * DIM], g_wql[QKV_N * DIM];
__device__ __nv_bfloat16 g_woh[DIM * DIM],   g_wol[DIM * DIM];
__device__ __nv_bfloat16 g_ah[SEQ * DIM],    g_al[SEQ * DIM];
__device__ __nv_bfloat16 g_qkvh[SEQ * QKV_N], g_qkvl[SEQ * QKV_N];  // V region: fp16 bits

// ===========================================================================
// Helpers
// ===========================================================================
__device__ __forceinline__ uint32_t smem_u32(const void* p) {
    uint32_t a;
    asm("{ .reg .u64 t; cvta.to.shared.u64 t, %1; cvt.u32.u64 %0, t; }"
        : "=r"(a) : "l"(p));
    return a;
}

__device__ __forceinline__ void split2(float f0, float f1, uint32_t& hi, uint32_t& lo) {
    asm("cvt.rn.bf16x2.f32 %0, %1, %2;" : "=r"(hi) : "f"(f1), "f"(f0));
    float h0 = __uint_as_float(hi << 16);
    float h1 = __uint_as_float(hi & 0xFFFF0000u);
    asm("cvt.rn.bf16x2.f32 %0, %1, %2;" : "=r"(lo) : "f"(f1 - h1), "f"(f0 - h0));
}

__device__ __forceinline__ uint32_t pack_f16(float f0, float f1) {
    uint32_t r;
    asm("cvt.rn.f16x2.f32 %0, %1, %2;" : "=r"(r) : "f"(f1), "f"(f0));
    return r;
}

#define CP_ASYNC16(dst, src) \
    asm volatile("cp.async.cg.shared.global [%0], [%1], 16;" :: "r"(dst), "l"(src) : "memory")
#define CP_COMMIT() asm volatile("cp.async.commit_group;" ::: "memory")
#define CP_WAIT(n)  asm volatile("cp.async.wait_group %0;" :: "n"(n) : "memory")

#define LDSM_X4(r0, r1, r2, r3, addr) \
    asm volatile("ldmatrix.sync.aligned.m8n8.x4.shared.b16 {%0,%1,%2,%3}, [%4];" \
                 : "=r"(r0), "=r"(r1), "=r"(r2), "=r"(r3) : "r"(addr))
#define LDSM_X4_T(r0, r1, r2, r3, addr) \
    asm volatile("ldmatrix.sync.aligned.m8n8.x4.trans.shared.b16 {%0,%1,%2,%3}, [%4];" \
                 : "=r"(r0), "=r"(r1), "=r"(r2), "=r"(r3) : "r"(addr))

#define MMA16816(c, a, b) \
    asm volatile("mma.sync.aligned.m16n8k16.row.col.f32.bf16.bf16.f32 " \
                 "{%0,%1,%2,%3}, {%4,%5,%6,%7}, {%8,%9}, {%0,%1,%2,%3};" \
                 : "+f"((c)[0]), "+f"((c)[1]), "+f"((c)[2]), "+f"((c)[3]) \
                 : "r"((a)[0]), "r"((a)[1]), "r"((a)[2]), "r"((a)[3]), \
                   "r"((b)[0]), "r"((b)[1]))

#define MMA16816H(c, a, b) \
    asm volatile("mma.sync.aligned.m16n8k16.row.col.f32.f16.f16.f32 " \
                 "{%0,%1,%2,%3}, {%4,%5,%6,%7}, {%8,%9}, {%0,%1,%2,%3};" \
                 : "+f"((c)[0]), "+f"((c)[1]), "+f"((c)[2]), "+f"((c)[3]) \
                 : "r"((a)[0]), "r"((a)[1]), "r"((a)[2]), "r"((a)[3]), \
                   "r"((b)[0]), "r"((b)[1]))

// ===========================================================================
// fp32 -> split bf16 (hi/lo)
// ===========================================================================
__global__ __launch_bounds__(256)
void split_f32(const float4* __restrict__ in, uint2* __restrict__ hi,
               uint2* __restrict__ lo, int n4)
{
    int i = blockIdx.x * blockDim.x + threadIdx.x;
    if (i >= n4) return;
    float4 v = in[i];
    uint32_t h01, l01, h23, l23;
    split2(v.x, v.y, h01, l01);
    split2(v.z, v.w, h23, l23);
    hi[i] = make_uint2(h01, h23);
    lo[i] = make_uint2(l01, l23);
}

// Split qkv: Q (scaled) and K -> bf16 hi/lo; V -> fp16 (stored in hi array)
__global__ __launch_bounds__(256)
void split_qkv_k(const float4* __restrict__ in, uint2* __restrict__ hi,
                 uint2* __restrict__ lo)
{
    int i = blockIdx.x * blockDim.x + threadIdx.x;
    const int n4 = SEQ * QKV_N / 4;
    if (i >= n4) return;
    int col = (i * 4) % QKV_N;
    float4 v = in[i];
    if (col < VOFF) {
        float s = (col < KOFF) ? 0.08838834764831845f : 1.0f;
        uint32_t h01, l01, h23, l23;
        split2(v.x * s, v.y * s, h01, l01);
        split2(v.z * s, v.w * s, h23, l23);
        hi[i] = make_uint2(h01, h23);
        lo[i] = make_uint2(l01, l23);
    } else {
        hi[i] = make_uint2(pack_f16(v.x, v.y), pack_f16(v.z, v.w));
    }
}

// ===========================================================================
// HMMA split-bf16 GEMM (NT): 512 threads, 16 warps (4M x 4N), warp tile 32x32,
// CTA tile 128x128, BK=64, 3-stage cp.async pipeline.
// ===========================================================================
#define TBM 128
#define TBN 128
#define TBK 64
#define SROW 144
#define SARR 18432
#define SSTG 73728
#define NSTG 3
#define GSM_TOTAL (NSTG * SSTG)   // 221184

__global__ __launch_bounds__(512, 1)
void gemm_hmma(const __nv_bfloat16* __restrict__ Ah, const __nv_bfloat16* __restrict__ Al,
               const __nv_bfloat16* __restrict__ Bh, const __nv_bfloat16* __restrict__ Bl,
               float* __restrict__ C, int N, int K)
{
    extern __shared__ char sm[];
    const uint32_t sb = smem_u32(sm);
    const int tid = threadIdx.x, lane = tid & 31, wid = tid >> 5;
    const int wm = wid & 3, wn = wid >> 2;     // 4 x 4 warp grid
    const int bx = blockIdx.x, by = blockIdx.y;

    const __nv_bfloat16* Ahp = Ah + (size_t)(by * TBM) * K;
    const __nv_bfloat16* Alp = Al + (size_t)(by * TBM) * K;
    const __nv_bfloat16* Bhp = Bh + (size_t)(bx * TBN) * K;
    const __nv_bfloat16* Blp = Bl + (size_t)(bx * TBN) * K;

    float acc[2][4][4];
    #pragma unroll
    for (int i = 0; i < 2; i++)
        #pragma unroll
        for (int j = 0; j < 4; j++)
            #pragma unroll
            for (int q = 0; q < 4; q++) acc[i][j][q] = 0.f;

    auto stage = [&](int s, int t) {
        const uint32_t sd = sb + s * SSTG;
        #pragma unroll
        for (int i = 0; i < 2; i++) {
            int idx = tid + i * 512;          // 0..1023
            int row = idx >> 3, c = idx & 7;
            size_t goff = (size_t)row * K + t * TBK + c * 8;
            uint32_t doff = row * SROW + c * 16;
            CP_ASYNC16(sd + doff,            Ahp + goff);
            CP_ASYNC16(sd + SARR + doff,     Alp + goff);
            CP_ASYNC16(sd + 2 * SARR + doff, Bhp + goff);
            CP_ASYNC16(sd + 3 * SARR + doff, Blp + goff);
        }
    };

    // base addresses for fragment loads (ks offset added per step)
    const uint32_t abase = (uint32_t)(wm * 32 + (lane & 15)) * SROW
                         + (uint32_t)((lane >> 4) * 8) * 2;
    const uint32_t bbase = 2 * SARR
                         + (uint32_t)(wn * 32 + (lane >> 4) * 8 + (lane & 7)) * SROW
                         + (uint32_t)(((lane >> 3) & 1) * 8) * 2;

    const int KT = K / TBK;
    stage(0, 0); CP_COMMIT();
    stage(1, 1); CP_COMMIT();

    int s = 0;
    for (int t = 0; t < KT; t++) {
        if (t + 2 < KT) {
            stage((s + 2) % NSTG, t + 2);
            CP_COMMIT();
            CP_WAIT(2);
        } else {
            CP_WAIT(0);
        }
        __syncthreads();

        const uint32_t sd = sb + s * SSTG;
        #pragma unroll
        for (int ks = 0; ks < 4; ks++) {
            uint32_t ah[2][4], al[2][4], bh[4][2], bl[4][2];
            #pragma unroll
            for (int mi = 0; mi < 2; mi++) {
                uint32_t addr = sd + abase + mi * 16 * SROW + ks * 32;
                LDSM_X4(ah[mi][0], ah[mi][1], ah[mi][2], ah[mi][3], addr);
                LDSM_X4(al[mi][0], al[mi][1], al[mi][2], al[mi][3], addr + SARR);
            }
            #pragma unroll
            for (int nj = 0; nj < 2; nj++) {
                uint32_t addr = sd + bbase + nj * 16 * SROW + ks * 32;
                LDSM_X4(bh[2 * nj][0], bh[2 * nj][1],
                        bh[2 * nj + 1][0], bh[2 * nj + 1][1], addr);
                LDSM_X4(bl[2 * nj][0], bl[2 * nj][1],
                        bl[2 * nj + 1][0], bl[2 * nj + 1][1], addr + SARR);
            }
            #pragma unroll
            for (int mi = 0; mi < 2; mi++)
                #pragma unroll
                for (int ni = 0; ni < 4; ni++) {
                    MMA16816(acc[mi][ni], ah[mi], bh[ni]);
                    MMA16816(acc[mi][ni], ah[mi], bl[ni]);
                    MMA16816(acc[mi][ni], al[mi], bh[ni]);
                }
        }
        __syncthreads();
        s = (s + 1) % NSTG;
    }

    // Epilogue: direct fp32 stores
    #pragma unroll
    for (int mi = 0; mi < 2; mi++) {
        #pragma unroll
        for (int ni = 0; ni < 4; ni++) {
            int r0 = by * TBM + wm * 32 + mi * 16 + (lane >> 2);
            int c0 = bx * TBN + wn * 32 + ni * 8 + (lane & 3) * 2;
            *(float2*)&C[(size_t)r0 * N + c0]       = make_float2(acc[mi][ni][0], acc[mi][ni][1]);
            *(float2*)&C[(size_t)(r0 + 8) * N + c0] = make_float2(acc[mi][ni][2], acc[mi][ni][3]);
        }
    }
}

// ---------------------------------------------------------------------------
// RoPE
// ---------------------------------------------------------------------------
__global__ __launch_bounds__(256)
void rope_kernel(float* __restrict__ qkv, const float* __restrict__ fc)
{
    int idx = blockIdx.x * blockDim.x + threadIdx.x;
    const int total = SEQ * (NH + NKV) * (HD / 2);
    if (idx >= total) return;

    int i  = idx & 63;
    int hh = (idx >> 6) % (NH + NKV);
    int s  = idx / ((NH + NKV) * 64);

    int c0 = (hh < NH) ? hh * HD : KOFF + (hh - NH) * HD;
    float* p = qkv + (size_t)s * QKV_N + c0 + 2 * i;

    float x0 = p[0], x1 = p[1];
    float c  = fc[s * HD + 2 * i + 0];
    float sn = fc[s * HD + 2 * i + 1];
    p[0] = x0 * c - x1 * sn;
    p[1] = x0 * sn + x1 * c;
}

// ===========================================================================
// HMMA flash attention (unchanged from R7 passing version)
// ===========================================================================
#define FROW 272
#define FS_Q    1536
#define FS_QL   18944
#define FS_KH(b) (36352 + (b) * 34816)
#define FS_KL(b) (FS_KH(b) + 17408)
#define FS_V(b)  (105984 + (b) * 17408)
#define FS_TOTAL 140800
#define OSS 132

__global__ __launch_bounds__(256)
void flash_hmma(const __nv_bfloat16* __restrict__ qh_g,
                const __nv_bfloat16* __restrict__ ql_g,
                __nv_bfloat16* __restrict__ oh, __nv_bfloat16* __restrict__ ol)
{
    extern __shared__ char sm[];
    const uint32_t sb = smem_u32(sm);
    float* m_run  = (float*)(sm);
    float* l_run  = (float*)(sm + 256);
    float* m_half = (float*)(sm + 512);
    float* l_half = (float*)(sm + 1024);

    const int qb = blockIdx.x, h = blockIdx.y, kvh = h >> 2;
    const int tid = threadIdx.x, lane = tid & 31, wid = tid >> 5;
    const int wm = wid & 3, wn = wid >> 2;

    #pragma unroll
    for (int i = 0; i < 4; i++) {
        int idx = tid + i * 256;
        int row = idx >> 4, c = idx & 15;
        size_t go = (size_t)(qb * 64 + row) * QKV_N + h * HD + c * 8;
        uint32_t so = (uint32_t)(row * FROW + c * 16);
        CP_ASYNC16(sb + FS_Q  + so, qh_g + go);
        CP_ASYNC16(sb + FS_QL + so, ql_g + go);
    }
    if (tid < 64) { m_run[tid] = -INFINITY; l_run[tid] = 0.f; }
    CP_COMMIT();

    auto stageKV = [&](int b, int kb) {
        #pragma unroll
        for (int i = 0; i < 4; i++) {
            int idx = tid + i * 256;
            int row = idx >> 4, c = idx & 15;
            size_t gk = (size_t)(kb * 64 + row) * QKV_N + KOFF + kvh * HD + c * 8;
            size_t gv = (size_t)(kb * 64 + row) * QKV_N + VOFF + kvh * HD + c * 8;
            uint32_t so = (uint32_t)(row * FROW + c * 16);
            CP_ASYNC16(sb + FS_KH(b) + so, qh_g + gk);
            CP_ASYNC16(sb + FS_KL(b) + so, ql_g + gk);
            CP_ASYNC16(sb + FS_V(b)  + so, qh_g + gv);
        }
    };

    stageKV(0, 0);
    CP_COMMIT();

    float oacc[16][4];
    #pragma unroll
    for (int g = 0; g < 16; g++)
        #pragma unroll
        for (int q = 0; q < 4; q++) oacc[g][q] = 0.f;

    const int r0g = wm * 16 + (lane >> 2);
    const int r1g = r0g + 8;

    const uint32_t qaddr = sb + FS_Q
        + (uint32_t)(wm * 16 + (lane & 15)) * FROW + (uint32_t)((lane >> 4) * 8) * 2;
    const uint32_t krel = (uint32_t)(wn * 32 + (lane >> 4) * 8 + (lane & 7)) * FROW
        + (uint32_t)(((lane >> 3) & 1) * 8) * 2;
    const uint32_t vrel = (uint32_t)(wn * 32 + ((lane >> 3) & 1) * 8 + (lane & 7)) * FROW
        + (uint32_t)((lane >> 4) * 8) * 2;

    for (int kb = 0; kb <= qb; kb++) {
        if (kb < qb) { stageKV((kb + 1) & 1, kb + 1); CP_COMMIT(); CP_WAIT(1); }
        else         { CP_WAIT(0); }
        __syncthreads();

        const int buf = kb & 1;
        const uint32_t kaddr = sb + FS_KH(buf) + krel;
        const uint32_t vaddr = sb + FS_V(buf) + vrel;

        float sacc[4][4];
        #pragma unroll
        for (int nb = 0; nb < 4; nb++)
            #pragma unroll
            for (int q = 0; q < 4; q++) sacc[nb][q] = 0.f;

        #pragma unroll
        for (int d16 = 0; d16 < 8; d16++) {
            uint32_t qhf[4], qlf[4], kh[2][4], kl[2][4];
            LDSM_X4(qhf[0], qhf[1], qhf[2], qhf[3], qaddr + d16 * 32);
            LDSM_X4(qlf[0], qlf[1], qlf[2], qlf[3], qaddr + d16 * 32 + (FS_QL - FS_Q));
            LDSM_X4(kh[0][0], kh[0][1], kh[0][2], kh[0][3], kaddr + d16 * 32);
            LDSM_X4(kh[1][0], kh[1][1], kh[1][2], kh[1][3], kaddr + d16 * 32 + 16 * FROW);
            LDSM_X4(kl[0][0], kl[0][1], kl[0][2], kl[0][3], kaddr + d16 * 32 + 17408);
            LDSM_X4(kl[1][0], kl[1][1], kl[1][2], kl[1][3], kaddr + d16 * 32 + 17408 + 16 * FROW);
            #pragma unroll
            for (int p = 0; p < 2; p++) {
                MMA16816(sacc[2 * p],     qhf, (&kh[p][0]));
                MMA16816(sacc[2 * p + 1], qhf, (&kh[p][2]));
                MMA16816(sacc[2 * p],     qhf, (&kl[p][0]));
                MMA16816(sacc[2 * p + 1], qhf, (&kl[p][2]));
                MMA16816(sacc[2 * p],     qlf, (&kh[p][0]));
                MMA16816(sacc[2 * p + 1], qlf, (&kh[p][2]));
            }
        }

        if (kb == qb) {
            const int rr0 = wm * 16 + (lane >> 2), rr1 = rr0 + 8;
            #pragma unroll
            for (int nb = 0; nb < 4; nb++) {
                int c = wn * 32 + nb * 8 + (lane & 3) * 2;
                if (c     > rr0) sacc[nb][0] = -1e30f;
                if (c + 1 > rr0) sacc[nb][1] = -1e30f;
                if (c     > rr1) sacc[nb][2] = -1e30f;
                if (c + 1 > rr1) sacc[nb][3] = -1e30f;
            }
        }

        float mx0 = -INFINITY, mx1 = -INFINITY;
        #pragma unroll
        for (int nb = 0; nb < 4; nb++) {
            mx0 = fmaxf(mx0, fmaxf(sacc[nb][0], sacc[nb][1]));
            mx1 = fmaxf(mx1, fmaxf(sacc[nb][2], sacc[nb][3]));
        }
        mx0 = fmaxf(mx0, __shfl_xor_sync(0xffffffffu, mx0, 1));
        mx0 = fmaxf(mx0, __shfl_xor_sync(0xffffffffu, mx0, 2));
        mx1 = fmaxf(mx1, __shfl_xor_sync(0xffffffffu, mx1, 1));
        mx1 = fmaxf(mx1, __shfl_xor_sync(0xffffffffu, mx1, 2));
        if ((lane & 3) == 0) {
            m_half[wn * 64 + r0g] = mx0;
            m_half[wn * 64 + r1g] = mx1;
        }
        __syncthreads();

        const float mo0 = m_run[r0g], mo1 = m_run[r1g];
        const float mn0 = fmaxf(mo0, fmaxf(m_half[r0g], m_half[64 + r0g]));
        const float mn1 = fmaxf(mo1, fmaxf(m_half[r1g], m_half[64 + r1g]));
        const float al0 = __expf(mo0 - mn0), al1 = __expf(mo1 - mn1);

        float ls0 = 0.f, ls1 = 0.f;
        #pragma unroll
        for (int nb = 0; nb < 4; nb++) {
            sacc[nb][0] = __expf(sacc[nb][0] - mn0);
            sacc[nb][1] = __expf(sacc[nb][1] - mn0);
            sacc[nb][2] = __expf(sacc[nb][2] - mn1);
            sacc[nb][3] = __expf(sacc[nb][3] - mn1);
            ls0 += sacc[nb][0] + sacc[nb][1];
            ls1 += sacc[nb][2] + sacc[nb][3];
        }
        ls0 += __shfl_xor_sync(0xffffffffu, ls0, 1);
        ls0 += __shfl_xor_sync(0xffffffffu, ls0, 2);
        ls1 += __shfl_xor_sync(0xffffffffu, ls1, 1);
        ls1 += __shfl_xor_sync(0xffffffffu, ls1, 2);
        if ((lane & 3) == 0) {
            l_half[wn * 64 + r0g] = ls0;
            l_half[wn * 64 + r1g] = ls1;
        }
        __syncthreads();
        if (wn == 0 && (lane & 3) == 0) {
            m_run[r0g] = mn0;
            m_run[r1g] = mn1;
            l_run[r0g] = l_run[r0g] * al0 + l_half[r0g] + l_half[64 + r0g];
            l_run[r1g] = l_run[r1g] * al1 + l_half[r1g] + l_half[64 + r1g];
        }

        #pragma unroll
        for (int g = 0; g < 16; g++) {
            oacc[g][0] *= al0; oacc[g][1] *= al0;
            oacc[g][2] *= al1; oacc[g][3] *= al1;
        }

        #pragma unroll
        for (int t = 0; t < 2; t++) {
            uint32_t a[4];
            a[0] = pack_f16(sacc[2 * t][0],     sacc[2 * t][1]);
            a[1] = pack_f16(sacc[2 * t][2],     sacc[2 * t][3]);
            a[2] = pack_f16(sacc[2 * t + 1][0], sacc[2 * t + 1][1]);
            a[3] = pack_f16(sacc[2 * t + 1][2], sacc[2 * t + 1][3]);
            #pragma unroll
            for (int g = 0; g < 8; g++) {
                uint32_t v[4];
                LDSM_X4_T(v[0], v[1], v[2], v[3], vaddr + t * 16 * FROW + g * 32);
                MMA16816H(oacc[2 * g],     a, (&v[0]));
                MMA16816H(oacc[2 * g + 1], a, (&v[2]));
            }
        }
    }

    __syncthreads();
    float* Os = (float*)(sm + FS_KH(0));
    if (wn == 0) {
        #pragma unroll
        for (int g = 0; g < 16; g++) {
            int c = g * 8 + (lane & 3) * 2;
            Os[r0g * OSS + c]     = oacc[g][0];
            Os[r0g * OSS + c + 1] = oacc[g][1];
            Os[r1g * OSS + c]     = oacc[g][2];
            Os[r1g * OSS + c + 1] = oacc[g][3];
        }
    }
    __syncthreads();
    if (wn == 1) {
        const float inv0 = 1.f / l_run[r0g];
        const float inv1 = 1.f / l_run[r1g];
        #pragma unroll
        for (int g = 0; g < 16; g++) {
            int c = g * 8 + (lane & 3) * 2;
            float v0 = (Os[r0g * OSS + c]     + oacc[g][0]) * inv0;
            float v1 = (Os[r0g * OSS + c + 1] + oacc[g][1]) * inv0;
            float v2 = (Os[r1g * OSS + c]     + oacc[g][2]) * inv1;
            float v3 = (Os[r1g * OSS + c + 1] + oacc[g][3]) * inv1;
            uint32_t hi0, lo0, hi1, lo1;
            split2(v0, v1, hi0, lo0);
            split2(v2, v3, hi1, lo1);
            size_t o0 = (size_t)(qb * 64 + r0g) * DIM + h * HD + c;
            size_t o1 = (size_t)(qb * 64 + r1g) * DIM + h * HD + c;
            *(uint32_t*)(oh + o0) = hi0; *(uint32_t*)(ol + o0) = lo0;
            *(uint32_t*)(oh + o1) = hi1; *(uint32_t*)(ol + o1) = lo1;
        }
    }
}

// ---------------------------------------------------------------------------
// Launch
// ---------------------------------------------------------------------------
extern "C" void kernel_launch(void* const* d_in, const int* in_sizes, int n_in,
                              void* d_out, int out_size)
{
    const float* x    = (const float*)d_in[0];
    const float* fc   = (const float*)d_in[1];
    const float* wqkv = (const float*)d_in[2];
    const float* wo   = (const float*)d_in[3];
    float* out = (float*)d_out;

    float* qkv = nullptr;
    __nv_bfloat16 *xh, *xl, *wqh, *wql, *woh, *wol, *ah, *al, *qkvh, *qkvl;
    cudaGetSymbolAddress((void**)&qkv,  g_qkv);
    cudaGetSymbolAddress((void**)&xh,   g_xh);
    cudaGetSymbolAddress((void**)&xl,   g_xl);
    cudaGetSymbolAddress((void**)&wqh,  g_wqh);
    cudaGetSymbolAddress((void**)&wql,  g_wql);
    cudaGetSymbolAddress((void**)&woh,  g_woh);
    cudaGetSymbolAddress((void**)&wol,  g_wol);
    cudaGetSymbolAddress((void**)&ah,   g_ah);
    cudaGetSymbolAddress((void**)&al,   g_al);
    cudaGetSymbolAddress((void**)&qkvh, g_qkvh);
    cudaGetSymbolAddress((void**)&qkvl, g_qkvl);

    static bool attr_set = false;
    if (!attr_set) {
        cudaFuncSetAttribute(gemm_hmma, cudaFuncAttributeMaxDynamicSharedMemorySize, GSM_TOTAL);
        cudaFuncSetAttribute(flash_hmma, cudaFuncAttributeMaxDynamicSharedMemorySize, FS_TOTAL);
        attr_set = true;
    }

    // 0) split fp32 inputs -> bf16 hi/lo
    {
        int n4;
        n4 = SEQ * DIM / 4;
        split_f32<<<(n4 + 255) / 256, 256>>>((const float4*)x, (uint2*)xh, (uint2*)xl, n4);
        n4 = QKV_N * DIM / 4;
        split_f32<<<(n4 + 255) / 256, 256>>>((const float4*)wqkv, (uint2*)wqh, (uint2*)wql, n4);
        n4 = DIM * DIM / 4;
        split_f32<<<(n4 + 255) / 256, 256>>>((const float4*)wo, (uint2*)woh, (uint2*)wol, n4);
    }

    // 1) qkv = x @ wqkv^T
    gemm_hmma<<<dim3(QKV_N / TBN, SEQ / TBM), 512, GSM_TOTAL>>>(xh, xl, wqh, wql, qkv, QKV_N, DIM);

    // 2) RoPE
    {
        int total = SEQ * (NH + NKV) * (HD / 2);
        rope_kernel<<<(total + 255) / 256, 256>>>(qkv, fc);
    }

    // 3) split qkv (Q scaled, K bf16 hi/lo, V fp16)
    {
        int n4 = SEQ * QKV_N / 4;
        split_qkv_k<<<(n4 + 255) / 256, 256>>>((const float4*)qkv, (uint2*)qkvh, (uint2*)qkvl);
    }

    // 4) HMMA flash attention
    flash_hmma<<<dim3(SEQ / 64, NH), 256, FS_TOTAL>>>(qkvh, qkvl, ah, al);

    // 5) out = attn @ wo^T
    gemm_hmma<<<dim3(DIM / TBN, SEQ / TBM), 512, GSM_TOTAL>>>(ah, al, woh, wol, out, DIM, DIM);
}

// round 10
// speedup vs baseline: 1.1610x; 1.1610x over previous
#include <cuda_runtime.h>
#include <cuda_bf16.h>
#include <cuda_fp16.h>
#include <math.h>
#include <stdint.h>

// Problem constants
#define SEQ   2048
#define DIM   4096
#define NH    32
#define NKV   8
#define HD    128
#define QKV_N 6144
#define KOFF  4096
#define VOFF  5120

// Scratch (__device__ globals). All half-precision scratch now holds fp16 bits.
__device__ float g_qkv[SEQ * QKV_N];
__device__ __half g_xh[SEQ * DIM],    g_xl[SEQ * DIM];
__device__ __half g_wqh[QKV_N * DIM], g_wql[QKV_N * DIM];
__device__ __half g_woh[DIM * DIM],   g_wol[DIM * DIM];
__device__ __half g_ah[SEQ * DIM];
__device__ __half g_qkvh[SEQ * QKV_N], g_qkvl[SEQ * QKV_N];

// ===========================================================================
// Helpers
// ===========================================================================
__device__ __forceinline__ uint32_t smem_u32(const void* p) {
    uint32_t a;
    asm("{ .reg .u64 t; cvta.to.shared.u64 t, %1; cvt.u32.u64 %0, t; }"
        : "=r"(a) : "l"(p));
    return a;
}

__device__ __forceinline__ uint32_t pack_f16(float f0, float f1) {
    uint32_t r;
    asm("cvt.rn.f16x2.f32 %0, %1, %2;" : "=r"(r) : "f"(f1), "f"(f0));
    return r;
}

// fp32 pair -> (hi, lo) fp16x2 packed
__device__ __forceinline__ void split2h(float f0, float f1, uint32_t& hi, uint32_t& lo) {
    hi = pack_f16(f0, f1);
    __half2 h = *reinterpret_cast<__half2*>(&hi);
    float h0 = __low2float(h), h1 = __high2float(h);
    lo = pack_f16(f0 - h0, f1 - h1);
}

#define CP_ASYNC16(dst, src) \
    asm volatile("cp.async.cg.shared.global [%0], [%1], 16;" :: "r"(dst), "l"(src) : "memory")
#define CP_COMMIT() asm volatile("cp.async.commit_group;" ::: "memory")
#define CP_WAIT(n)  asm volatile("cp.async.wait_group %0;" :: "n"(n) : "memory")

#define LDSM_X4(r0, r1, r2, r3, addr) \
    asm volatile("ldmatrix.sync.aligned.m8n8.x4.shared.b16 {%0,%1,%2,%3}, [%4];" \
                 : "=r"(r0), "=r"(r1), "=r"(r2), "=r"(r3) : "r"(addr))
#define LDSM_X4_T(r0, r1, r2, r3, addr) \
    asm volatile("ldmatrix.sync.aligned.m8n8.x4.trans.shared.b16 {%0,%1,%2,%3}, [%4];" \
                 : "=r"(r0), "=r"(r1), "=r"(r2), "=r"(r3) : "r"(addr))

#define MMA16816H(c, a, b) \
    asm volatile("mma.sync.aligned.m16n8k16.row.col.f32.f16.f16.f32 " \
                 "{%0,%1,%2,%3}, {%4,%5,%6,%7}, {%8,%9}, {%0,%1,%2,%3};" \
                 : "+f"((c)[0]), "+f"((c)[1]), "+f"((c)[2]), "+f"((c)[3]) \
                 : "r"((a)[0]), "r"((a)[1]), "r"((a)[2]), "r"((a)[3]), \
                   "r"((b)[0]), "r"((b)[1]))

// ===========================================================================
// fp32 -> split fp16 (hi/lo)
// ===========================================================================
__global__ __launch_bounds__(256)
void split_f32h(const float4* __restrict__ in, uint2* __restrict__ hi,
                uint2* __restrict__ lo, int n4)
{
    int i = blockIdx.x * blockDim.x + threadIdx.x;
    if (i >= n4) return;
    float4 v = in[i];
    uint32_t h01, l01, h23, l23;
    split2h(v.x, v.y, h01, l01);
    split2h(v.z, v.w, h23, l23);
    hi[i] = make_uint2(h01, h23);
    lo[i] = make_uint2(l01, l23);
}

// Fused RoPE + split: Q (rope+scale) / K (rope) -> fp16 hi/lo; V -> fp16 hi only.
__global__ __launch_bounds__(256)
void rope_split(const float4* __restrict__ in, const float* __restrict__ fc,
                uint2* __restrict__ hi, uint2* __restrict__ lo)
{
    int i = blockIdx.x * blockDim.x + threadIdx.x;
    const int n4 = SEQ * QKV_N / 4;
    if (i >= n4) return;
    int col = (i * 4) % QKV_N;
    int s   = (i * 4) / QKV_N;
    float4 v = in[i];
    if (col < VOFF) {
        int d = col & 127;                    // even, pairs (d,d+1),(d+2,d+3)
        const float* f = fc + s * HD + d;     // fc[s][d/2] = (cos,sin)
        float c0 = f[0], s0 = f[1], c1 = f[2], s1 = f[3];
        float r0 = v.x * c0 - v.y * s0, r1 = v.x * s0 + v.y * c0;
        float r2 = v.z * c1 - v.w * s1, r3 = v.z * s1 + v.w * c1;
        float sc = (col < KOFF) ? 0.08838834764831845f : 1.0f;
        uint32_t h01, l01, h23, l23;
        split2h(r0 * sc, r1 * sc, h01, l01);
        split2h(r2 * sc, r3 * sc, h23, l23);
        hi[i] = make_uint2(h01, h23);
        lo[i] = make_uint2(l01, l23);
    } else {
        hi[i] = make_uint2(pack_f16(v.x, v.y), pack_f16(v.z, v.w));
    }
}

// ===========================================================================
// 3-pass split-fp16 GEMM (NT) — R7 geometry: 256 thr, 8 warps (4Mx2N),
// warp tile 32x64, BK=64, 2-stage cp.async, frag double-buffered.
// ===========================================================================
#define TBM 128
#define TBN 128
#define TBK 64
#define SROW 144
#define SARR 18432
#define SSTG 73728
#define GSM_TOTAL 147456

__global__ __launch_bounds__(256)
void gemm_hmma3(const __half* __restrict__ Ah, const __half* __restrict__ Al,
                const __half* __restrict__ Bh, const __half* __restrict__ Bl,
                float* __restrict__ C, int N, int K)
{
    extern __shared__ char sm[];
    const uint32_t sb = smem_u32(sm);
    const int tid = threadIdx.x, lane = tid & 31, wid = tid >> 5;
    const int wm = wid & 3, wn = wid >> 2;
    const int bx = blockIdx.x, by = blockIdx.y;

    const __half* Ahp = Ah + (size_t)(by * TBM) * K;
    const __half* Alp = Al + (size_t)(by * TBM) * K;
    const __half* Bhp = Bh + (size_t)(bx * TBN) * K;
    const __half* Blp = Bl + (size_t)(bx * TBN) * K;

    float acc[2][8][4];
    #pragma unroll
    for (int i = 0; i < 2; i++)
        #pragma unroll
        for (int j = 0; j < 8; j++)
            #pragma unroll
            for (int q = 0; q < 4; q++) acc[i][j][q] = 0.f;

    auto stage = [&](int s, int t) {
        const uint32_t sd = sb + s * SSTG;
        #pragma unroll
        for (int i = 0; i < 4; i++) {
            int idx = tid + i * 256;
            int row = idx >> 3, c = idx & 7;
            size_t goff = (size_t)row * K + t * TBK + c * 8;
            uint32_t doff = row * SROW + c * 16;
            CP_ASYNC16(sd + doff,            Ahp + goff);
            CP_ASYNC16(sd + SARR + doff,     Alp + goff);
            CP_ASYNC16(sd + 2 * SARR + doff, Bhp + goff);
            CP_ASYNC16(sd + 3 * SARR + doff, Blp + goff);
        }
    };

    uint32_t ah[2][2][4], al[2][2][4], bh[2][8][2], bl[2][8][2];

    auto ldfrag = [&](int s, int ks, int buf) {
        const uint32_t sd = sb + s * SSTG;
        #pragma unroll
        for (int mi = 0; mi < 2; mi++) {
            uint32_t addr = sd + (uint32_t)(wm * 32 + mi * 16 + (lane & 15)) * SROW
                          + (uint32_t)(ks * 16 + (lane >> 4) * 8) * 2;
            LDSM_X4(ah[buf][mi][0], ah[buf][mi][1], ah[buf][mi][2], ah[buf][mi][3], addr);
            LDSM_X4(al[buf][mi][0], al[buf][mi][1], al[buf][mi][2], al[buf][mi][3], addr + SARR);
        }
        #pragma unroll
        for (int nj = 0; nj < 4; nj++) {
            int half_ = lane >> 4, r8 = (lane >> 3) & 1;
            uint32_t addr = sd + 2 * SARR
                          + (uint32_t)(wn * 64 + nj * 16 + half_ * 8 + (lane & 7)) * SROW
                          + (uint32_t)(ks * 16 + r8 * 8) * 2;
            LDSM_X4(bh[buf][2 * nj][0], bh[buf][2 * nj][1],
                    bh[buf][2 * nj + 1][0], bh[buf][2 * nj + 1][1], addr);
            LDSM_X4(bl[buf][2 * nj][0], bl[buf][2 * nj][1],
                    bl[buf][2 * nj + 1][0], bl[buf][2 * nj + 1][1], addr + SARR);
        }
    };

    auto mmastep = [&](int buf) {
        #pragma unroll
        for (int mi = 0; mi < 2; mi++)
            #pragma unroll
            for (int ni = 0; ni < 8; ni++) {
                MMA16816H(acc[mi][ni], ah[buf][mi], bh[buf][ni]);
                MMA16816H(acc[mi][ni], ah[buf][mi], bl[buf][ni]);
                MMA16816H(acc[mi][ni], al[buf][mi], bh[buf][ni]);
            }
    };

    const int KT = K / TBK;
    stage(0, 0);
    CP_COMMIT();
    for (int t = 0; t < KT; t++) {
        if (t + 1 < KT) {
            stage((t + 1) & 1, t + 1);
            CP_COMMIT();
            CP_WAIT(1);
        } else {
            CP_WAIT(0);
        }
        __syncthreads();

        const int s = t & 1;
        ldfrag(s, 0, 0);
        #pragma unroll
        for (int ks = 0; ks < 4; ks++) {
            const int cur = ks & 1;
            if (ks < 3) ldfrag(s, ks + 1, cur ^ 1);
            mmastep(cur);
        }
        __syncthreads();
    }

    #pragma unroll
    for (int mi = 0; mi < 2; mi++) {
        #pragma unroll
        for (int ni = 0; ni < 8; ni++) {
            int r0 = by * TBM + wm * 32 + mi * 16 + (lane >> 2);
            int c0 = bx * TBN + wn * 64 + ni * 8 + (lane & 3) * 2;
            *(float2*)&C[(size_t)r0 * N + c0]       = make_float2(acc[mi][ni][0], acc[mi][ni][1]);
            *(float2*)&C[(size_t)(r0 + 8) * N + c0] = make_float2(acc[mi][ni][2], acc[mi][ni][3]);
        }
    }
}

// ===========================================================================
// 2-pass GEMM (NT): C = Ah*(Bh + Bl). A is fp16 hi only. Same geometry.
// ===========================================================================
#define SSTG2 55296              // 3 arrays per stage
#define GSM2_TOTAL 110592

__global__ __launch_bounds__(256)
void gemm_hmma2(const __half* __restrict__ Ah,
                const __half* __restrict__ Bh, const __half* __restrict__ Bl,
                float* __restrict__ C, int N, int K)
{
    extern __shared__ char sm[];
    const uint32_t sb = smem_u32(sm);
    const int tid = threadIdx.x, lane = tid & 31, wid = tid >> 5;
    const int wm = wid & 3, wn = wid >> 2;
    const int bx = blockIdx.x, by = blockIdx.y;

    const __half* Ahp = Ah + (size_t)(by * TBM) * K;
    const __half* Bhp = Bh + (size_t)(bx * TBN) * K;
    const __half* Blp = Bl + (size_t)(bx * TBN) * K;

    float acc[2][8][4];
    #pragma unroll
    for (int i = 0; i < 2; i++)
        #pragma unroll
        for (int j = 0; j < 8; j++)
            #pragma unroll
            for (int q = 0; q < 4; q++) acc[i][j][q] = 0.f;

    auto stage = [&](int s, int t) {
        const uint32_t sd = sb + s * SSTG2;
        #pragma unroll
        for (int i = 0; i < 4; i++) {
            int idx = tid + i * 256;
            int row = idx >> 3, c = idx & 7;
            size_t goff = (size_t)row * K + t * TBK + c * 8;
            uint32_t doff = row * SROW + c * 16;
            CP_ASYNC16(sd + doff,            Ahp + goff);
            CP_ASYNC16(sd + SARR + doff,     Bhp + goff);
            CP_ASYNC16(sd + 2 * SARR + doff, Blp + goff);
        }
    };

    uint32_t ah[2][2][4], bh[2][8][2], bl[2][8][2];

    auto ldfrag = [&](int s, int ks, int buf) {
        const uint32_t sd = sb + s * SSTG2;
        #pragma unroll
        for (int mi = 0; mi < 2; mi++) {
            uint32_t addr = sd + (uint32_t)(wm * 32 + mi * 16 + (lane & 15)) * SROW
                          + (uint32_t)(ks * 16 + (lane >> 4) * 8) * 2;
            LDSM_X4(ah[buf][mi][0], ah[buf][mi][1], ah[buf][mi][2], ah[buf][mi][3], addr);
        }
        #pragma unroll
        for (int nj = 0; nj < 4; nj++) {
            int half_ = lane >> 4, r8 = (lane >> 3) & 1;
            uint32_t addr = sd + SARR
                          + (uint32_t)(wn * 64 + nj * 16 + half_ * 8 + (lane & 7)) * SROW
                          + (uint32_t)(ks * 16 + r8 * 8) * 2;
            LDSM_X4(bh[buf][2 * nj][0], bh[buf][2 * nj][1],
                    bh[buf][2 * nj + 1][0], bh[buf][2 * nj + 1][1], addr);
            LDSM_X4(bl[buf][2 * nj][0], bl[buf][2 * nj][1],
                    bl[buf][2 * nj + 1][0], bl[buf][2 * nj + 1][1], addr + SARR);
        }
    };

    auto mmastep = [&](int buf) {
        #pragma unroll
        for (int mi = 0; mi < 2; mi++)
            #pragma unroll
            for (int ni = 0; ni < 8; ni++) {
                MMA16816H(acc[mi][ni], ah[buf][mi], bh[buf][ni]);
                MMA16816H(acc[mi][ni], ah[buf][mi], bl[buf][ni]);
            }
    };

    const int KT = K / TBK;
    stage(0, 0);
    CP_COMMIT();
    for (int t = 0; t < KT; t++) {
        if (t + 1 < KT) {
            stage((t + 1) & 1, t + 1);
            CP_COMMIT();
            CP_WAIT(1);
        } else {
            CP_WAIT(0);
        }
        __syncthreads();

        const int s = t & 1;
        ldfrag(s, 0, 0);
        #pragma unroll
        for (int ks = 0; ks < 4; ks++) {
            const int cur = ks & 1;
            if (ks < 3) ldfrag(s, ks + 1, cur ^ 1);
            mmastep(cur);
        }
        __syncthreads();
    }

    #pragma unroll
    for (int mi = 0; mi < 2; mi++) {
        #pragma unroll
        for (int ni = 0; ni < 8; ni++) {
            int r0 = by * TBM + wm * 32 + mi * 16 + (lane >> 2);
            int c0 = bx * TBN + wn * 64 + ni * 8 + (lane & 3) * 2;
            *(float2*)&C[(size_t)r0 * N + c0]       = make_float2(acc[mi][ni][0], acc[mi][ni][1]);
            *(float2*)&C[(size_t)(r0 + 8) * N + c0] = make_float2(acc[mi][ni][2], acc[mi][ni][3]);
        }
    }
}

// ===========================================================================
// HMMA flash attention (fp16 split S, fp16 PV). Epilogue: fp16 hi only.
// ===========================================================================
#define FROW 272
#define FS_Q    1536
#define FS_QL   18944
#define FS_KH(b) (36352 + (b) * 34816)
#define FS_KL(b) (FS_KH(b) + 17408)
#define FS_V(b)  (105984 + (b) * 17408)
#define FS_TOTAL 140800
#define OSS 132

__global__ __launch_bounds__(256)
void flash_hmma(const __half* __restrict__ qh_g, const __half* __restrict__ ql_g,
                __half* __restrict__ oh)
{
    extern __shared__ char sm[];
    const uint32_t sb = smem_u32(sm);
    float* m_run  = (float*)(sm);
    float* l_run  = (float*)(sm + 256);
    float* m_half = (float*)(sm + 512);
    float* l_half = (float*)(sm + 1024);

    const int qb = blockIdx.x, h = blockIdx.y, kvh = h >> 2;
    const int tid = threadIdx.x, lane = tid & 31, wid = tid >> 5;
    const int wm = wid & 3, wn = wid >> 2;

    #pragma unroll
    for (int i = 0; i < 4; i++) {
        int idx = tid + i * 256;
        int row = idx >> 4, c = idx & 15;
        size_t go = (size_t)(qb * 64 + row) * QKV_N + h * HD + c * 8;
        uint32_t so = (uint32_t)(row * FROW + c * 16);
        CP_ASYNC16(sb + FS_Q  + so, qh_g + go);
        CP_ASYNC16(sb + FS_QL + so, ql_g + go);
    }
    if (tid < 64) { m_run[tid] = -INFINITY; l_run[tid] = 0.f; }
    CP_COMMIT();

    auto stageKV = [&](int b, int kb) {
        #pragma unroll
        for (int i = 0; i < 4; i++) {
            int idx = tid + i * 256;
            int row = idx >> 4, c = idx & 15;
            size_t gk = (size_t)(kb * 64 + row) * QKV_N + KOFF + kvh * HD + c * 8;
            size_t gv = (size_t)(kb * 64 + row) * QKV_N + VOFF + kvh * HD + c * 8;
            uint32_t so = (uint32_t)(row * FROW + c * 16);
            CP_ASYNC16(sb + FS_KH(b) + so, qh_g + gk);
            CP_ASYNC16(sb + FS_KL(b) + so, ql_g + gk);
            CP_ASYNC16(sb + FS_V(b)  + so, qh_g + gv);
        }
    };

    stageKV(0, 0);
    CP_COMMIT();

    float oacc[16][4];
    #pragma unroll
    for (int g = 0; g < 16; g++)
        #pragma unroll
        for (int q = 0; q < 4; q++) oacc[g][q] = 0.f;

    const int r0g = wm * 16 + (lane >> 2);
    const int r1g = r0g + 8;

    const uint32_t qaddr = sb + FS_Q
        + (uint32_t)(wm * 16 + (lane & 15)) * FROW + (uint32_t)((lane >> 4) * 8) * 2;
    const uint32_t krel = (uint32_t)(wn * 32 + (lane >> 4) * 8 + (lane & 7)) * FROW
        + (uint32_t)(((lane >> 3) & 1) * 8) * 2;
    const uint32_t vrel = (uint32_t)(wn * 32 + ((lane >> 3) & 1) * 8 + (lane & 7)) * FROW
        + (uint32_t)((lane >> 4) * 8) * 2;

    for (int kb = 0; kb <= qb; kb++) {
        if (kb < qb) { stageKV((kb + 1) & 1, kb + 1); CP_COMMIT(); CP_WAIT(1); }
        else         { CP_WAIT(0); }
        __syncthreads();

        const int buf = kb & 1;
        const uint32_t kaddr = sb + FS_KH(buf) + krel;
        const uint32_t vaddr = sb + FS_V(buf) + vrel;

        float sacc[4][4];
        #pragma unroll
        for (int nb = 0; nb < 4; nb++)
            #pragma unroll
            for (int q = 0; q < 4; q++) sacc[nb][q] = 0.f;

        #pragma unroll
        for (int d16 = 0; d16 < 8; d16++) {
            uint32_t qhf[4], qlf[4], kh[2][4], kl[2][4];
            LDSM_X4(qhf[0], qhf[1], qhf[2], qhf[3], qaddr + d16 * 32);
            LDSM_X4(qlf[0], qlf[1], qlf[2], qlf[3], qaddr + d16 * 32 + (FS_QL - FS_Q));
            LDSM_X4(kh[0][0], kh[0][1], kh[0][2], kh[0][3], kaddr + d16 * 32);
            LDSM_X4(kh[1][0], kh[1][1], kh[1][2], kh[1][3], kaddr + d16 * 32 + 16 * FROW);
            LDSM_X4(kl[0][0], kl[0][1], kl[0][2], kl[0][3], kaddr + d16 * 32 + 17408);
            LDSM_X4(kl[1][0], kl[1][1], kl[1][2], kl[1][3], kaddr + d16 * 32 + 17408 + 16 * FROW);
            #pragma unroll
            for (int p = 0; p < 2; p++) {
                MMA16816H(sacc[2 * p],     qhf, (&kh[p][0]));
                MMA16816H(sacc[2 * p + 1], qhf, (&kh[p][2]));
                MMA16816H(sacc[2 * p],     qhf, (&kl[p][0]));
                MMA16816H(sacc[2 * p + 1], qhf, (&kl[p][2]));
                MMA16816H(sacc[2 * p],     qlf, (&kh[p][0]));
                MMA16816H(sacc[2 * p + 1], qlf, (&kh[p][2]));
            }
        }

        if (kb == qb) {
            const int rr0 = wm * 16 + (lane >> 2), rr1 = rr0 + 8;
            #pragma unroll
            for (int nb = 0; nb < 4; nb++) {
                int c = wn * 32 + nb * 8 + (lane & 3) * 2;
                if (c     > rr0) sacc[nb][0] = -1e30f;
                if (c + 1 > rr0) sacc[nb][1] = -1e30f;
                if (c     > rr1) sacc[nb][2] = -1e30f;
                if (c + 1 > rr1) sacc[nb][3] = -1e30f;
            }
        }

        float mx0 = -INFINITY, mx1 = -INFINITY;
        #pragma unroll
        for (int nb = 0; nb < 4; nb++) {
            mx0 = fmaxf(mx0, fmaxf(sacc[nb][0], sacc[nb][1]));
            mx1 = fmaxf(mx1, fmaxf(sacc[nb][2], sacc[nb][3]));
        }
        mx0 = fmaxf(mx0, __shfl_xor_sync(0xffffffffu, mx0, 1));
        mx0 = fmaxf(mx0, __shfl_xor_sync(0xffffffffu, mx0, 2));
        mx1 = fmaxf(mx1, __shfl_xor_sync(0xffffffffu, mx1, 1));
        mx1 = fmaxf(mx1, __shfl_xor_sync(0xffffffffu, mx1, 2));
        if ((lane & 3) == 0) {
            m_half[wn * 64 + r0g] = mx0;
            m_half[wn * 64 + r1g] = mx1;
        }
        __syncthreads();

        const float mo0 = m_run[r0g], mo1 = m_run[r1g];
        const float mn0 = fmaxf(mo0, fmaxf(m_half[r0g], m_half[64 + r0g]));
        const float mn1 = fmaxf(mo1, fmaxf(m_half[r1g], m_half[64 + r1g]));
        const float al0 = __expf(mo0 - mn0), al1 = __expf(mo1 - mn1);

        float ls0 = 0.f, ls1 = 0.f;
        #pragma unroll
        for (int nb = 0; nb < 4; nb++) {
            sacc[nb][0] = __expf(sacc[nb][0] - mn0);
            sacc[nb][1] = __expf(sacc[nb][1] - mn0);
            sacc[nb][2] = __expf(sacc[nb][2] - mn1);
            sacc[nb][3] = __expf(sacc[nb][3] - mn1);
            ls0 += sacc[nb][0] + sacc[nb][1];
            ls1 += sacc[nb][2] + sacc[nb][3];
        }
        ls0 += __shfl_xor_sync(0xffffffffu, ls0, 1);
        ls0 += __shfl_xor_sync(0xffffffffu, ls0, 2);
        ls1 += __shfl_xor_sync(0xffffffffu, ls1, 1);
        ls1 += __shfl_xor_sync(0xffffffffu, ls1, 2);
        if ((lane & 3) == 0) {
            l_half[wn * 64 + r0g] = ls0;
            l_half[wn * 64 + r1g] = ls1;
        }
        __syncthreads();
        if (wn == 0 && (lane & 3) == 0) {
            m_run[r0g] = mn0;
            m_run[r1g] = mn1;
            l_run[r0g] = l_run[r0g] * al0 + l_half[r0g] + l_half[64 + r0g];
            l_run[r1g] = l_run[r1g] * al1 + l_half[r1g] + l_half[64 + r1g];
        }

        #pragma unroll
        for (int g = 0; g < 16; g++) {
            oacc[g][0] *= al0; oacc[g][1] *= al0;
            oacc[g][2] *= al1; oacc[g][3] *= al1;
        }

        #pragma unroll
        for (int t = 0; t < 2; t++) {
            uint32_t a[4];
            a[0] = pack_f16(sacc[2 * t][0],     sacc[2 * t][1]);
            a[1] = pack_f16(sacc[2 * t][2],     sacc[2 * t][3]);
            a[2] = pack_f16(sacc[2 * t + 1][0], sacc[2 * t + 1][1]);
            a[3] = pack_f16(sacc[2 * t + 1][2], sacc[2 * t + 1][3]);
            #pragma unroll
            for (int g = 0; g < 8; g++) {
                uint32_t v[4];
                LDSM_X4_T(v[0], v[1], v[2], v[3], vaddr + t * 16 * FROW + g * 32);
                MMA16816H(oacc[2 * g],     a, (&v[0]));
                MMA16816H(oacc[2 * g + 1], a, (&v[2]));
            }
        }
    }

    __syncthreads();
    float* Os = (float*)(sm + FS_KH(0));
    if (wn == 0) {
        #pragma unroll
        for (int g = 0; g < 16; g++) {
            int c = g * 8 + (lane & 3) * 2;
            Os[r0g * OSS + c]     = oacc[g][0];
            Os[r0g * OSS + c + 1] = oacc[g][1];
            Os[r1g * OSS + c]     = oacc[g][2];
            Os[r1g * OSS + c + 1] = oacc[g][3];
        }
    }
    __syncthreads();
    if (wn == 1) {
        const float inv0 = 1.f / l_run[r0g];
        const float inv1 = 1.f / l_run[r1g];
        #pragma unroll
        for (int g = 0; g < 16; g++) {
            int c = g * 8 + (lane & 3) * 2;
            float v0 = (Os[r0g * OSS + c]     + oacc[g][0]) * inv0;
            float v1 = (Os[r0g * OSS + c + 1] + oacc[g][1]) * inv0;
            float v2 = (Os[r1g * OSS + c]     + oacc[g][2]) * inv1;
            float v3 = (Os[r1g * OSS + c + 1] + oacc[g][3]) * inv1;
            size_t o0 = (size_t)(qb * 64 + r0g) * DIM + h * HD + c;
            size_t o1 = (size_t)(qb * 64 + r1g) * DIM + h * HD + c;
            *(uint32_t*)(oh + o0) = pack_f16(v0, v1);
            *(uint32_t*)(oh + o1) = pack_f16(v2, v3);
        }
    }
}

// ---------------------------------------------------------------------------
// Launch
// ---------------------------------------------------------------------------
extern "C" void kernel_launch(void* const* d_in, const int* in_sizes, int n_in,
                              void* d_out, int out_size)
{
    const float* x    = (const float*)d_in[0];
    const float* fc   = (const float*)d_in[1];
    const float* wqkv = (const float*)d_in[2];
    const float* wo   = (const float*)d_in[3];
    float* out = (float*)d_out;

    float* qkv = nullptr;
    __half *xh, *xl, *wqh, *wql, *woh, *wol, *ah, *qkvh, *qkvl;
    cudaGetSymbolAddress((void**)&qkv,  g_qkv);
    cudaGetSymbolAddress((void**)&xh,   g_xh);
    cudaGetSymbolAddress((void**)&xl,   g_xl);
    cudaGetSymbolAddress((void**)&wqh,  g_wqh);
    cudaGetSymbolAddress((void**)&wql,  g_wql);
    cudaGetSymbolAddress((void**)&woh,  g_woh);
    cudaGetSymbolAddress((void**)&wol,  g_wol);
    cudaGetSymbolAddress((void**)&ah,   g_ah);
    cudaGetSymbolAddress((void**)&qkvh, g_qkvh);
    cudaGetSymbolAddress((void**)&qkvl, g_qkvl);

    static bool attr_set = false;
    if (!attr_set) {
        cudaFuncSetAttribute(gemm_hmma3, cudaFuncAttributeMaxDynamicSharedMemorySize, GSM_TOTAL);
        cudaFuncSetAttribute(gemm_hmma2, cudaFuncAttributeMaxDynamicSharedMemorySize, GSM2_TOTAL);
        cudaFuncSetAttribute(flash_hmma, cudaFuncAttributeMaxDynamicSharedMemorySize, FS_TOTAL);
        attr_set = true;
    }

    // 0) split fp32 inputs -> fp16 hi/lo
    {
        int n4;
        n4 = SEQ * DIM / 4;
        split_f32h<<<(n4 + 255) / 256, 256>>>((const float4*)x, (uint2*)xh, (uint2*)xl, n4);
        n4 = QKV_N * DIM / 4;
        split_f32h<<<(n4 + 255) / 256, 256>>>((const float4*)wqkv, (uint2*)wqh, (uint2*)wql, n4);
        n4 = DIM * DIM / 4;
        split_f32h<<<(n4 + 255) / 256, 256>>>((const float4*)wo, (uint2*)woh, (uint2*)wol, n4);
    }

    // 1) qkv = x @ wqkv^T  (3-pass split-fp16)
    gemm_hmma3<<<dim3(QKV_N / TBN, SEQ / TBM), 256, GSM_TOTAL>>>(xh, xl, wqh, wql, qkv, QKV_N, DIM);

    // 2) fused RoPE + split qkv -> fp16 hi/lo (Q scaled; V hi only)
    {
        int n4 = SEQ * QKV_N / 4;
        rope_split<<<(n4 + 255) / 256, 256>>>((const float4*)qkv, fc, (uint2*)qkvh, (uint2*)qkvl);
    }

    // 3) HMMA flash attention (writes fp16 attn hi)
    flash_hmma<<<dim3(SEQ / 64, NH), 256, FS_TOTAL>>>(qkvh, qkvl, ah);

    // 4) out = attn @ wo^T  (2-pass: Ah*(Wh+Wl))
    gemm_hmma2<<<dim3(DIM / TBN, SEQ / TBM), 256, GSM2_TOTAL>>>(ah, woh, wol, out, DIM, DIM);
}

// round 14
// speedup vs baseline: 1.3947x; 1.2013x over previous
#include <cuda_runtime.h>
#include <cuda_bf16.h>
#include <cuda_fp16.h>
#include <math.h>
#include <stdint.h>

// Problem constants
#define SEQ   2048
#define DIM   4096
#define NH    32
#define NKV   8
#define HD    128
#define QKV_N 6144
#define KOFF  4096
#define VOFF  5120

// Scratch (__device__ globals), fp16 bits
__device__ float g_qkv[SEQ * QKV_N];
__device__ __half g_xh[SEQ * DIM],    g_xl[SEQ * DIM];
__device__ __half g_wqh[QKV_N * DIM], g_wql[QKV_N * DIM];
__device__ __half g_woh[DIM * DIM],   g_wol[DIM * DIM];
__device__ __half g_ah[SEQ * DIM];
__device__ __half g_qkvh[SEQ * QKV_N], g_qkvl[SEQ * QKV_N];

// ===========================================================================
// Helpers
// ===========================================================================
__device__ __forceinline__ uint32_t smem_u32(const void* p) {
    uint32_t a;
    asm("{ .reg .u64 t; cvta.to.shared.u64 t, %1; cvt.u32.u64 %0, t; }"
        : "=r"(a) : "l"(p));
    return a;
}

__device__ __forceinline__ uint32_t pack_f16(float f0, float f1) {
    uint32_t r;
    asm("cvt.rn.f16x2.f32 %0, %1, %2;" : "=r"(r) : "f"(f1), "f"(f0));
    return r;
}

__device__ __forceinline__ void split2h(float f0, float f1, uint32_t& hi, uint32_t& lo) {
    hi = pack_f16(f0, f1);
    __half2 h = *reinterpret_cast<__half2*>(&hi);
    float h0 = __low2float(h), h1 = __high2float(h);
    lo = pack_f16(f0 - h0, f1 - h1);
}

#define CP_ASYNC16(dst, src) \
    asm volatile("cp.async.cg.shared.global [%0], [%1], 16;" :: "r"(dst), "l"(src) : "memory")
#define CP_COMMIT() asm volatile("cp.async.commit_group;" ::: "memory")
#define CP_WAIT(n)  asm volatile("cp.async.wait_group %0;" :: "n"(n) : "memory")

#define LDSM_X4(r0, r1, r2, r3, addr) \
    asm volatile("ldmatrix.sync.aligned.m8n8.x4.shared.b16 {%0,%1,%2,%3}, [%4];" \
                 : "=r"(r0), "=r"(r1), "=r"(r2), "=r"(r3) : "r"(addr))
#define LDSM_X4_T(r0, r1, r2, r3, addr) \
    asm volatile("ldmatrix.sync.aligned.m8n8.x4.trans.shared.b16 {%0,%1,%2,%3}, [%4];" \
                 : "=r"(r0), "=r"(r1), "=r"(r2), "=r"(r3) : "r"(addr))

#define MMA16816H(c, a, b) \
    asm volatile("mma.sync.aligned.m16n8k16.row.col.f32.f16.f16.f32 " \
                 "{%0,%1,%2,%3}, {%4,%5,%6,%7}, {%8,%9}, {%0,%1,%2,%3};" \
                 : "+f"((c)[0]), "+f"((c)[1]), "+f"((c)[2]), "+f"((c)[3]) \
                 : "r"((a)[0]), "r"((a)[1]), "r"((a)[2]), "r"((a)[3]), \
                   "r"((b)[0]), "r"((b)[1]))

// ===========================================================================
// fp32 -> split fp16 (hi/lo)
// ===========================================================================
__global__ __launch_bounds__(256)
void split_f32h(const float4* __restrict__ in, uint2* __restrict__ hi,
                uint2* __restrict__ lo, int n4)
{
    int i = blockIdx.x * blockDim.x + threadIdx.x;
    if (i >= n4) return;
    float4 v = in[i];
    uint32_t h01, l01, h23, l23;
    split2h(v.x, v.y, h01, l01);
    split2h(v.z, v.w, h23, l23);
    hi[i] = make_uint2(h01, h23);
    lo[i] = make_uint2(l01, l23);
}

// fp32 -> fp16 (hi only), for x
__global__ __launch_bounds__(256)
void conv_f32h(const float4* __restrict__ in, uint2* __restrict__ hi, int n4)
{
    int i = blockIdx.x * blockDim.x + threadIdx.x;
    if (i >= n4) return;
    float4 v = in[i];
    hi[i] = make_uint2(pack_f16(v.x, v.y), pack_f16(v.z, v.w));
}

// Fused RoPE + split: Q (rope+scale) / K (rope) -> fp16 hi/lo; V -> fp16 hi only.
__global__ __launch_bounds__(256)
void rope_split(const float4* __restrict__ in, const float* __restrict__ fc,
                uint2* __restrict__ hi, uint2* __restrict__ lo)
{
    int i = blockIdx.x * blockDim.x + threadIdx.x;
    const int n4 = SEQ * QKV_N / 4;
    if (i >= n4) return;
    int col = (i * 4) % QKV_N;
    int s   = (i * 4) / QKV_N;
    float4 v = in[i];
    if (col < VOFF) {
        int d = col & 127;
        const float* f = fc + s * HD + d;
        float c0 = f[0], s0 = f[1], c1 = f[2], s1 = f[3];
        float r0 = v.x * c0 - v.y * s0, r1 = v.x * s0 + v.y * c0;
        float r2 = v.z * c1 - v.w * s1, r3 = v.z * s1 + v.w * c1;
        float sc = (col < KOFF) ? 0.08838834764831845f : 1.0f;
        uint32_t h01, l01, h23, l23;
        split2h(r0 * sc, r1 * sc, h01, l01);
        split2h(r2 * sc, r3 * sc, h23, l23);
        hi[i] = make_uint2(h01, h23);
        lo[i] = make_uint2(l01, l23);
    } else {
        hi[i] = make_uint2(pack_f16(v.x, v.y), pack_f16(v.z, v.w));
    }
}

// ===========================================================================
// 2-pass GEMM (NT): C = Ah*(Bh + Bl). 256 thr, 8 warps (4Mx2N), warp 32x64,
// BK=64, 3-stage cp.async pipeline, frag double-buffered.
// ===========================================================================
#define TBM 128
#define TBN 128
#define TBK 64
#define SROW 144
#define SARR 18432
#define SSTG2 55296
#define NSTG2 3
#define GSM2_TOTAL (NSTG2 * SSTG2)   // 165888

__global__ __launch_bounds__(256)
void gemm_hmma2(const __half* __restrict__ Ah,
                const __half* __restrict__ Bh, const __half* __restrict__ Bl,
                float* __restrict__ C, int N, int K)
{
    extern __shared__ char sm[];
    const uint32_t sb = smem_u32(sm);
    const int tid = threadIdx.x, lane = tid & 31, wid = tid >> 5;
    const int wm = wid & 3, wn = wid >> 2;
    const int bx = blockIdx.x, by = blockIdx.y;

    const __half* Ahp = Ah + (size_t)(by * TBM) * K;
    const __half* Bhp = Bh + (size_t)(bx * TBN) * K;
    const __half* Blp = Bl + (size_t)(bx * TBN) * K;

    float acc[2][8][4];
    #pragma unroll
    for (int i = 0; i < 2; i++)
        #pragma unroll
        for (int j = 0; j < 8; j++)
            #pragma unroll
            for (int q = 0; q < 4; q++) acc[i][j][q] = 0.f;

    auto stage = [&](int s, int t) {
        const uint32_t sd = sb + s * SSTG2;
        #pragma unroll
        for (int i = 0; i < 4; i++) {
            int idx = tid + i * 256;
            int row = idx >> 3, c = idx & 7;
            size_t goff = (size_t)row * K + t * TBK + c * 8;
            uint32_t doff = row * SROW + c * 16;
            CP_ASYNC16(sd + doff,            Ahp + goff);
            CP_ASYNC16(sd + SARR + doff,     Bhp + goff);
            CP_ASYNC16(sd + 2 * SARR + doff, Blp + goff);
        }
    };

    uint32_t ah[2][2][4], bh[2][8][2], bl[2][8][2];

    auto ldfrag = [&](int s, int ks, int buf) {
        const uint32_t sd = sb + s * SSTG2;
        #pragma unroll
        for (int mi = 0; mi < 2; mi++) {
            uint32_t addr = sd + (uint32_t)(wm * 32 + mi * 16 + (lane & 15)) * SROW
                          + (uint32_t)(ks * 16 + (lane >> 4) * 8) * 2;
            LDSM_X4(ah[buf][mi][0], ah[buf][mi][1], ah[buf][mi][2], ah[buf][mi][3], addr);
        }
        #pragma unroll
        for (int nj = 0; nj < 4; nj++) {
            int half_ = lane >> 4, r8 = (lane >> 3) & 1;
            uint32_t addr = sd + SARR
                          + (uint32_t)(wn * 64 + nj * 16 + half_ * 8 + (lane & 7)) * SROW
                          + (uint32_t)(ks * 16 + r8 * 8) * 2;
            LDSM_X4(bh[buf][2 * nj][0], bh[buf][2 * nj][1],
                    bh[buf][2 * nj + 1][0], bh[buf][2 * nj + 1][1], addr);
            LDSM_X4(bl[buf][2 * nj][0], bl[buf][2 * nj][1],
                    bl[buf][2 * nj + 1][0], bl[buf][2 * nj + 1][1], addr + SARR);
        }
    };

    auto mmastep = [&](int buf) {
        #pragma unroll
        for (int mi = 0; mi < 2; mi++)
            #pragma unroll
            for (int ni = 0; ni < 8; ni++) {
                MMA16816H(acc[mi][ni], ah[buf][mi], bh[buf][ni]);
                MMA16816H(acc[mi][ni], ah[buf][mi], bl[buf][ni]);
            }
    };

    const int KT = K / TBK;
    stage(0, 0); CP_COMMIT();
    stage(1, 1); CP_COMMIT();

    int s = 0;
    for (int t = 0; t < KT; t++) {
        if (t + 2 < KT) {
            stage((s + 2) % NSTG2, t + 2);
            CP_COMMIT();
            CP_WAIT(2);
        } else {
            CP_WAIT(0);
        }
        __syncthreads();

        ldfrag(s, 0, 0);
        #pragma unroll
        for (int ks = 0; ks < 4; ks++) {
            const int cur = ks & 1;
            if (ks < 3) ldfrag(s, ks + 1, cur ^ 1);
            mmastep(cur);
        }
        __syncthreads();
        s = (s + 1) % NSTG2;
    }

    #pragma unroll
    for (int mi = 0; mi < 2; mi++) {
        #pragma unroll
        for (int ni = 0; ni < 8; ni++) {
            int r0 = by * TBM + wm * 32 + mi * 16 + (lane >> 2);
            int c0 = bx * TBN + wn * 64 + ni * 8 + (lane & 3) * 2;
            *(float2*)&C[(size_t)r0 * N + c0]       = make_float2(acc[mi][ni][0], acc[mi][ni][1]);
            *(float2*)&C[(size_t)(r0 + 8) * N + c0] = make_float2(acc[mi][ni][2], acc[mi][ni][3]);
        }
    }
}

// ===========================================================================
// HMMA flash attention (unchanged from R10)
// ===========================================================================
#define FROW 272
#define FS_Q    1536
#define FS_QL   18944
#define FS_KH(b) (36352 + (b) * 34816)
#define FS_KL(b) (FS_KH(b) + 17408)
#define FS_V(b)  (105984 + (b) * 17408)
#define FS_TOTAL 140800
#define OSS 132

__global__ __launch_bounds__(256)
void flash_hmma(const __half* __restrict__ qh_g, const __half* __restrict__ ql_g,
                __half* __restrict__ oh)
{
    extern __shared__ char sm[];
    const uint32_t sb = smem_u32(sm);
    float* m_run  = (float*)(sm);
    float* l_run  = (float*)(sm + 256);
    float* m_half = (float*)(sm + 512);
    float* l_half = (float*)(sm + 1024);

    const int qb = blockIdx.x, h = blockIdx.y, kvh = h >> 2;
    const int tid = threadIdx.x, lane = tid & 31, wid = tid >> 5;
    const int wm = wid & 3, wn = wid >> 2;

    #pragma unroll
    for (int i = 0; i < 4; i++) {
        int idx = tid + i * 256;
        int row = idx >> 4, c = idx & 15;
        size_t go = (size_t)(qb * 64 + row) * QKV_N + h * HD + c * 8;
        uint32_t so = (uint32_t)(row * FROW + c * 16);
        CP_ASYNC16(sb + FS_Q  + so, qh_g + go);
        CP_ASYNC16(sb + FS_QL + so, ql_g + go);
    }
    if (tid < 64) { m_run[tid] = -INFINITY; l_run[tid] = 0.f; }
    CP_COMMIT();

    auto stageKV = [&](int b, int kb) {
        #pragma unroll
        for (int i = 0; i < 4; i++) {
            int idx = tid + i * 256;
            int row = idx >> 4, c = idx & 15;
            size_t gk = (size_t)(kb * 64 + row) * QKV_N + KOFF + kvh * HD + c * 8;
            size_t gv = (size_t)(kb * 64 + row) * QKV_N + VOFF + kvh * HD + c * 8;
            uint32_t so = (uint32_t)(row * FROW + c * 16);
            CP_ASYNC16(sb + FS_KH(b) + so, qh_g + gk);
            CP_ASYNC16(sb + FS_KL(b) + so, ql_g + gk);
            CP_ASYNC16(sb + FS_V(b)  + so, qh_g + gv);
        }
    };

    stageKV(0, 0);
    CP_COMMIT();

    float oacc[16][4];
    #pragma unroll
    for (int g = 0; g < 16; g++)
        #pragma unroll
        for (int q = 0; q < 4; q++) oacc[g][q] = 0.f;

    const int r0g = wm * 16 + (lane >> 2);
    const int r1g = r0g + 8;

    const uint32_t qaddr = sb + FS_Q
        + (uint32_t)(wm * 16 + (lane & 15)) * FROW + (uint32_t)((lane >> 4) * 8) * 2;
    const uint32_t krel = (uint32_t)(wn * 32 + (lane >> 4) * 8 + (lane & 7)) * FROW
        + (uint32_t)(((lane >> 3) & 1) * 8) * 2;
    const uint32_t vrel = (uint32_t)(wn * 32 + ((lane >> 3) & 1) * 8 + (lane & 7)) * FROW
        + (uint32_t)((lane >> 4) * 8) * 2;

    for (int kb = 0; kb <= qb; kb++) {
        if (kb < qb) { stageKV((kb + 1) & 1, kb + 1); CP_COMMIT(); CP_WAIT(1); }
        else         { CP_WAIT(0); }
        __syncthreads();

        const int buf = kb & 1;
        const uint32_t kaddr = sb + FS_KH(buf) + krel;
        const uint32_t vaddr = sb + FS_V(buf) + vrel;

        float sacc[4][4];
        #pragma unroll
        for (int nb = 0; nb < 4; nb++)
            #pragma unroll
            for (int q = 0; q < 4; q++) sacc[nb][q] = 0.f;

        #pragma unroll
        for (int d16 = 0; d16 < 8; d16++) {
            uint32_t qhf[4], qlf[4], kh[2][4], kl[2][4];
            LDSM_X4(qhf[0], qhf[1], qhf[2], qhf[3], qaddr + d16 * 32);
            LDSM_X4(qlf[0], qlf[1], qlf[2], qlf[3], qaddr + d16 * 32 + (FS_QL - FS_Q));
            LDSM_X4(kh[0][0], kh[0][1], kh[0][2], kh[0][3], kaddr + d16 * 32);
            LDSM_X4(kh[1][0], kh[1][1], kh[1][2], kh[1][3], kaddr + d16 * 32 + 16 * FROW);
            LDSM_X4(kl[0][0], kl[0][1], kl[0][2], kl[0][3], kaddr + d16 * 32 + 17408);
            LDSM_X4(kl[1][0], kl[1][1], kl[1][2], kl[1][3], kaddr + d16 * 32 + 17408 + 16 * FROW);
            #pragma unroll
            for (int p = 0; p < 2; p++) {
                MMA16816H(sacc[2 * p],     qhf, (&kh[p][0]));
                MMA16816H(sacc[2 * p + 1], qhf, (&kh[p][2]));
                MMA16816H(sacc[2 * p],     qhf, (&kl[p][0]));
                MMA16816H(sacc[2 * p + 1], qhf, (&kl[p][2]));
                MMA16816H(sacc[2 * p],     qlf, (&kh[p][0]));
                MMA16816H(sacc[2 * p + 1], qlf, (&kh[p][2]));
            }
        }

        if (kb == qb) {
            const int rr0 = wm * 16 + (lane >> 2), rr1 = rr0 + 8;
            #pragma unroll
            for (int nb = 0; nb < 4; nb++) {
                int c = wn * 32 + nb * 8 + (lane & 3) * 2;
                if (c     > rr0) sacc[nb][0] = -1e30f;
                if (c + 1 > rr0) sacc[nb][1] = -1e30f;
                if (c     > rr1) sacc[nb][2] = -1e30f;
                if (c + 1 > rr1) sacc[nb][3] = -1e30f;
            }
        }

        float mx0 = -INFINITY, mx1 = -INFINITY;
        #pragma unroll
        for (int nb = 0; nb < 4; nb++) {
            mx0 = fmaxf(mx0, fmaxf(sacc[nb][0], sacc[nb][1]));
            mx1 = fmaxf(mx1, fmaxf(sacc[nb][2], sacc[nb][3]));
        }
        mx0 = fmaxf(mx0, __shfl_xor_sync(0xffffffffu, mx0, 1));
        mx0 = fmaxf(mx0, __shfl_xor_sync(0xffffffffu, mx0, 2));
        mx1 = fmaxf(mx1, __shfl_xor_sync(0xffffffffu, mx1, 1));
        mx1 = fmaxf(mx1, __shfl_xor_sync(0xffffffffu, mx1, 2));
        if ((lane & 3) == 0) {
            m_half[wn * 64 + r0g] = mx0;
            m_half[wn * 64 + r1g] = mx1;
        }
        __syncthreads();

        const float mo0 = m_run[r0g], mo1 = m_run[r1g];
        const float mn0 = fmaxf(mo0, fmaxf(m_half[r0g], m_half[64 + r0g]));
        const float mn1 = fmaxf(mo1, fmaxf(m_half[r1g], m_half[64 + r1g]));
        const float al0 = __expf(mo0 - mn0), al1 = __expf(mo1 - mn1);

        float ls0 = 0.f, ls1 = 0.f;
        #pragma unroll
        for (int nb = 0; nb < 4; nb++) {
            sacc[nb][0] = __expf(sacc[nb][0] - mn0);
            sacc[nb][1] = __expf(sacc[nb][1] - mn0);
            sacc[nb][2] = __expf(sacc[nb][2] - mn1);
            sacc[nb][3] = __expf(sacc[nb][3] - mn1);
            ls0 += sacc[nb][0] + sacc[nb][1];
            ls1 += sacc[nb][2] + sacc[nb][3];
        }
        ls0 += __shfl_xor_sync(0xffffffffu, ls0, 1);
        ls0 += __shfl_xor_sync(0xffffffffu, ls0, 2);
        ls1 += __shfl_xor_sync(0xffffffffu, ls1, 1);
        ls1 += __shfl_xor_sync(0xffffffffu, ls1, 2);
        if ((lane & 3) == 0) {
            l_half[wn * 64 + r0g] = ls0;
            l_half[wn * 64 + r1g] = ls1;
        }
        __syncthreads();
        if (wn == 0 && (lane & 3) == 0) {
            m_run[r0g] = mn0;
            m_run[r1g] = mn1;
            l_run[r0g] = l_run[r0g] * al0 + l_half[r0g] + l_half[64 + r0g];
            l_run[r1g] = l_run[r1g] * al1 + l_half[r1g] + l_half[64 + r1g];
        }

        #pragma unroll
        for (int g = 0; g < 16; g++) {
            oacc[g][0] *= al0; oacc[g][1] *= al0;
            oacc[g][2] *= al1; oacc[g][3] *= al1;
        }

        #pragma unroll
        for (int t = 0; t < 2; t++) {
            uint32_t a[4];
            a[0] = pack_f16(sacc[2 * t][0],     sacc[2 * t][1]);
            a[1] = pack_f16(sacc[2 * t][2],     sacc[2 * t][3]);
            a[2] = pack_f16(sacc[2 * t + 1][0], sacc[2 * t + 1][1]);
            a[3] = pack_f16(sacc[2 * t + 1][2], sacc[2 * t + 1][3]);
            #pragma unroll
            for (int g = 0; g < 8; g++) {
                uint32_t v[4];
                LDSM_X4_T(v[0], v[1], v[2], v[3], vaddr + t * 16 * FROW + g * 32);
                MMA16816H(oacc[2 * g],     a, (&v[0]));
                MMA16816H(oacc[2 * g + 1], a, (&v[2]));
            }
        }
    }

    __syncthreads();
    float* Os = (float*)(sm + FS_KH(0));
    if (wn == 0) {
        #pragma unroll
        for (int g = 0; g < 16; g++) {
            int c = g * 8 + (lane & 3) * 2;
            Os[r0g * OSS + c]     = oacc[g][0];
            Os[r0g * OSS + c + 1] = oacc[g][1];
            Os[r1g * OSS + c]     = oacc[g][2];
            Os[r1g * OSS + c + 1] = oacc[g][3];
        }
    }
    __syncthreads();
    if (wn == 1) {
        const float inv0 = 1.f / l_run[r0g];
        const float inv1 = 1.f / l_run[r1g];
        #pragma unroll
        for (int g = 0; g < 16; g++) {
            int c = g * 8 + (lane & 3) * 2;
            float v0 = (Os[r0g * OSS + c]     + oacc[g][0]) * inv0;
            float v1 = (Os[r0g * OSS + c + 1] + oacc[g][1]) * inv0;
            float v2 = (Os[r1g * OSS + c]     + oacc[g][2]) * inv1;
            float v3 = (Os[r1g * OSS + c + 1] + oacc[g][3]) * inv1;
            size_t o0 = (size_t)(qb * 64 + r0g) * DIM + h * HD + c;
            size_t o1 = (size_t)(qb * 64 + r1g) * DIM + h * HD + c;
            *(uint32_t*)(oh + o0) = pack_f16(v0, v1);
            *(uint32_t*)(oh + o1) = pack_f16(v2, v3);
        }
    }
}

// ---------------------------------------------------------------------------
// Launch
// ---------------------------------------------------------------------------
extern "C" void kernel_launch(void* const* d_in, const int* in_sizes, int n_in,
                              void* d_out, int out_size)
{
    const float* x    = (const float*)d_in[0];
    const float* fc   = (const float*)d_in[1];
    const float* wqkv = (const float*)d_in[2];
    const float* wo   = (const float*)d_in[3];
    float* out = (float*)d_out;

    float* qkv = nullptr;
    __half *xh, *wqh, *wql, *woh, *wol, *ah, *qkvh, *qkvl;
    cudaGetSymbolAddress((void**)&qkv,  g_qkv);
    cudaGetSymbolAddress((void**)&xh,   g_xh);
    cudaGetSymbolAddress((void**)&wqh,  g_wqh);
    cudaGetSymbolAddress((void**)&wql,  g_wql);
    cudaGetSymbolAddress((void**)&woh,  g_woh);
    cudaGetSymbolAddress((void**)&wol,  g_wol);
    cudaGetSymbolAddress((void**)&ah,   g_ah);
    cudaGetSymbolAddress((void**)&qkvh, g_qkvh);
    cudaGetSymbolAddress((void**)&qkvl, g_qkvl);

    static bool attr_set = false;
    if (!attr_set) {
        cudaFuncSetAttribute(gemm_hmma2, cudaFuncAttributeMaxDynamicSharedMemorySize, GSM2_TOTAL);
        cudaFuncSetAttribute(flash_hmma, cudaFuncAttributeMaxDynamicSharedMemorySize, FS_TOTAL);
        attr_set = true;
    }

    // 0) convert/split fp32 inputs
    {
        int n4;
        n4 = SEQ * DIM / 4;
        conv_f32h<<<(n4 + 255) / 256, 256>>>((const float4*)x, (uint2*)xh, n4);
        n4 = QKV_N * DIM / 4;
        split_f32h<<<(n4 + 255) / 256, 256>>>((const float4*)wqkv, (uint2*)wqh, (uint2*)wql, n4);
        n4 = DIM * DIM / 4;
        split_f32h<<<(n4 + 255) / 256, 256>>>((const float4*)wo, (uint2*)woh, (uint2*)wol, n4);
    }

    // 1) qkv = xh @ (Wh+Wl)^T  (2-pass split-fp16)
    gemm_hmma2<<<dim3(QKV_N / TBN, SEQ / TBM), 256, GSM2_TOTAL>>>(xh, wqh, wql, qkv, QKV_N, DIM);

    // 2) fused RoPE + split qkv -> fp16 hi/lo (Q scaled; V hi only)
    {
        int n4 = SEQ * QKV_N / 4;
        rope_split<<<(n4 + 255) / 256, 256>>>((const float4*)qkv, fc, (uint2*)qkvh, (uint2*)qkvl);
    }

    // 3) HMMA flash attention (writes fp16 attn hi)
    flash_hmma<<<dim3(SEQ / 64, NH), 256, FS_TOTAL>>>(qkvh, qkvl, ah);

    // 4) out = attn @ wo^T  (2-pass)
    gemm_hmma2<<<dim3(DIM / TBN, SEQ / TBM), 256, GSM2_TOTAL>>>(ah, woh, wol, out, DIM, DIM);
}

// round 16
// speedup vs baseline: 1.9994x; 1.4335x over previous
#include <cuda_runtime.h>
#include <cuda_bf16.h>
#include <cuda_fp16.h>
#include <math.h>
#include <stdint.h>

// Problem constants
#define SEQ   2048
#define DIM   4096
#define NH    32
#define NKV   8
#define HD    128
#define QKV_N 6144
#define KOFF  4096
#define VOFF  5120

// Scratch (__device__ globals), fp16 bits
__device__ float g_qkv[SEQ * QKV_N];
__device__ __half g_xh[SEQ * DIM];
__device__ __half g_wqh[QKV_N * DIM];
__device__ __half g_woh[DIM * DIM];
__device__ __half g_ah[SEQ * DIM];
__device__ __half g_qkvh[SEQ * QKV_N], g_qkvl[SEQ * QKV_N];

// ===========================================================================
// Helpers
// ===========================================================================
__device__ __forceinline__ uint32_t smem_u32(const void* p) {
    uint32_t a;
    asm("{ .reg .u64 t; cvta.to.shared.u64 t, %1; cvt.u32.u64 %0, t; }"
        : "=r"(a) : "l"(p));
    return a;
}

__device__ __forceinline__ uint32_t pack_f16(float f0, float f1) {
    uint32_t r;
    asm("cvt.rn.f16x2.f32 %0, %1, %2;" : "=r"(r) : "f"(f1), "f"(f0));
    return r;
}

__device__ __forceinline__ void split2h(float f0, float f1, uint32_t& hi, uint32_t& lo) {
    hi = pack_f16(f0, f1);
    __half2 h = *reinterpret_cast<__half2*>(&hi);
    float h0 = __low2float(h), h1 = __high2float(h);
    lo = pack_f16(f0 - h0, f1 - h1);
}

#define CP_ASYNC16(dst, src) \
    asm volatile("cp.async.cg.shared.global [%0], [%1], 16;" :: "r"(dst), "l"(src) : "memory")
#define CP_COMMIT() asm volatile("cp.async.commit_group;" ::: "memory")
#define CP_WAIT(n)  asm volatile("cp.async.wait_group %0;" :: "n"(n) : "memory")

#define LDSM_X4(r0, r1, r2, r3, addr) \
    asm volatile("ldmatrix.sync.aligned.m8n8.x4.shared.b16 {%0,%1,%2,%3}, [%4];" \
                 : "=r"(r0), "=r"(r1), "=r"(r2), "=r"(r3) : "r"(addr))
#define LDSM_X4_T(r0, r1, r2, r3, addr) \
    asm volatile("ldmatrix.sync.aligned.m8n8.x4.trans.shared.b16 {%0,%1,%2,%3}, [%4];" \
                 : "=r"(r0), "=r"(r1), "=r"(r2), "=r"(r3) : "r"(addr))

#define MMA16816H(c, a, b) \
    asm volatile("mma.sync.aligned.m16n8k16.row.col.f32.f16.f16.f32 " \
                 "{%0,%1,%2,%3}, {%4,%5,%6,%7}, {%8,%9}, {%0,%1,%2,%3};" \
                 : "+f"((c)[0]), "+f"((c)[1]), "+f"((c)[2]), "+f"((c)[3]) \
                 : "r"((a)[0]), "r"((a)[1]), "r"((a)[2]), "r"((a)[3]), \
                   "r"((b)[0]), "r"((b)[1]))

// ===========================================================================
// fp32 -> fp16 (round-to-nearest)
// ===========================================================================
__global__ __launch_bounds__(256)
void conv_f32h(const float4* __restrict__ in, uint2* __restrict__ hi, int n4)
{
    int i = blockIdx.x * blockDim.x + threadIdx.x;
    if (i >= n4) return;
    float4 v = in[i];
    hi[i] = make_uint2(pack_f16(v.x, v.y), pack_f16(v.z, v.w));
}

// Fused RoPE + split: Q (rope+scale) / K (rope) -> fp16 hi/lo; V -> fp16 hi only.
__global__ __launch_bounds__(256)
void rope_split(const float4* __restrict__ in, const float* __restrict__ fc,
                uint2* __restrict__ hi, uint2* __restrict__ lo)
{
    int i = blockIdx.x * blockDim.x + threadIdx.x;
    const int n4 = SEQ * QKV_N / 4;
    if (i >= n4) return;
    int col = (i * 4) % QKV_N;
    int s   = (i * 4) / QKV_N;
    float4 v = in[i];
    if (col < VOFF) {
        int d = col & 127;
        const float* f = fc + s * HD + d;
        float c0 = f[0], s0 = f[1], c1 = f[2], s1 = f[3];
        float r0 = v.x * c0 - v.y * s0, r1 = v.x * s0 + v.y * c0;
        float r2 = v.z * c1 - v.w * s1, r3 = v.z * s1 + v.w * c1;
        float sc = (col < KOFF) ? 0.08838834764831845f : 1.0f;
        uint32_t h01, l01, h23, l23;
        split2h(r0 * sc, r1 * sc, h01, l01);
        split2h(r2 * sc, r3 * sc, h23, l23);
        hi[i] = make_uint2(h01, h23);
        lo[i] = make_uint2(l01, l23);
    } else {
        hi[i] = make_uint2(pack_f16(v.x, v.y), pack_f16(v.z, v.w));
    }
}

// ===========================================================================
// 1-pass fp16 GEMM (NT): C = Ah * Bh^T. 256 thr, 8 warps (4Mx2N),
// warp tile 32x64, BK=64, 4-stage cp.async pipeline, frag double-buffered.
// ===========================================================================
#define TBM 128
#define TBN 128
#define TBK 64
#define SROW 144
#define SARR 18432
#define SSTG1 36864
#define NSTG1 4
#define GSM1_TOTAL (NSTG1 * SSTG1)   // 147456

__global__ __launch_bounds__(256)
void gemm_hmma1(const __half* __restrict__ Ah, const __half* __restrict__ Bh,
                float* __restrict__ C, int N, int K)
{
    extern __shared__ char sm[];
    const uint32_t sb = smem_u32(sm);
    const int tid = threadIdx.x, lane = tid & 31, wid = tid >> 5;
    const int wm = wid & 3, wn = wid >> 2;
    const int bx = blockIdx.x, by = blockIdx.y;

    const __half* Ahp = Ah + (size_t)(by * TBM) * K;
    const __half* Bhp = Bh + (size_t)(bx * TBN) * K;

    float acc[2][8][4];
    #pragma unroll
    for (int i = 0; i < 2; i++)
        #pragma unroll
        for (int j = 0; j < 8; j++)
            #pragma unroll
            for (int q = 0; q < 4; q++) acc[i][j][q] = 0.f;

    auto stage = [&](int s, int t) {
        const uint32_t sd = sb + s * SSTG1;
        #pragma unroll
        for (int i = 0; i < 4; i++) {
            int idx = tid + i * 256;
            int row = idx >> 3, c = idx & 7;
            size_t goff = (size_t)row * K + t * TBK + c * 8;
            uint32_t doff = row * SROW + c * 16;
            CP_ASYNC16(sd + doff,        Ahp + goff);
            CP_ASYNC16(sd + SARR + doff, Bhp + goff);
        }
    };

    uint32_t ah[2][2][4], bh[2][8][2];

    auto ldfrag = [&](int s, int ks, int buf) {
        const uint32_t sd = sb + s * SSTG1;
        #pragma unroll
        for (int mi = 0; mi < 2; mi++) {
            uint32_t addr = sd + (uint32_t)(wm * 32 + mi * 16 + (lane & 15)) * SROW
                          + (uint32_t)(ks * 16 + (lane >> 4) * 8) * 2;
            LDSM_X4(ah[buf][mi][0], ah[buf][mi][1], ah[buf][mi][2], ah[buf][mi][3], addr);
        }
        #pragma unroll
        for (int nj = 0; nj < 4; nj++) {
            int half_ = lane >> 4, r8 = (lane >> 3) & 1;
            uint32_t addr = sd + SARR
                          + (uint32_t)(wn * 64 + nj * 16 + half_ * 8 + (lane & 7)) * SROW
                          + (uint32_t)(ks * 16 + r8 * 8) * 2;
            LDSM_X4(bh[buf][2 * nj][0], bh[buf][2 * nj][1],
                    bh[buf][2 * nj + 1][0], bh[buf][2 * nj + 1][1], addr);
        }
    };

    auto mmastep = [&](int buf) {
        #pragma unroll
        for (int mi = 0; mi < 2; mi++)
            #pragma unroll
            for (int ni = 0; ni < 8; ni++)
                MMA16816H(acc[mi][ni], ah[buf][mi], bh[buf][ni]);
    };

    const int KT = K / TBK;
    stage(0, 0); CP_COMMIT();
    stage(1, 1); CP_COMMIT();
    stage(2, 2); CP_COMMIT();

    int s = 0;
    for (int t = 0; t < KT; t++) {
        if (t + 3 < KT) {
            stage((s + 3) % NSTG1, t + 3);
            CP_COMMIT();
            CP_WAIT(3);
        } else {
            CP_WAIT(0);
        }
        __syncthreads();

        ldfrag(s, 0, 0);
        #pragma unroll
        for (int ks = 0; ks < 4; ks++) {
            const int cur = ks & 1;
            if (ks < 3) ldfrag(s, ks + 1, cur ^ 1);
            mmastep(cur);
        }
        __syncthreads();
        s = (s + 1) % NSTG1;
    }

    #pragma unroll
    for (int mi = 0; mi < 2; mi++) {
        #pragma unroll
        for (int ni = 0; ni < 8; ni++) {
            int r0 = by * TBM + wm * 32 + mi * 16 + (lane >> 2);
            int c0 = bx * TBN + wn * 64 + ni * 8 + (lane & 3) * 2;
            *(float2*)&C[(size_t)r0 * N + c0]       = make_float2(acc[mi][ni][0], acc[mi][ni][1]);
            *(float2*)&C[(size_t)(r0 + 8) * N + c0] = make_float2(acc[mi][ni][2], acc[mi][ni][3]);
        }
    }
}

// ===========================================================================
// HMMA flash attention (unchanged from R14 passing version)
// ===========================================================================
#define FROW 272
#define FS_Q    1536
#define FS_QL   18944
#define FS_KH(b) (36352 + (b) * 34816)
#define FS_KL(b) (FS_KH(b) + 17408)
#define FS_V(b)  (105984 + (b) * 17408)
#define FS_TOTAL 140800
#define OSS 132

__global__ __launch_bounds__(256)
void flash_hmma(const __half* __restrict__ qh_g, const __half* __restrict__ ql_g,
                __half* __restrict__ oh)
{
    extern __shared__ char sm[];
    const uint32_t sb = smem_u32(sm);
    float* m_run  = (float*)(sm);
    float* l_run  = (float*)(sm + 256);
    float* m_half = (float*)(sm + 512);
    float* l_half = (float*)(sm + 1024);

    const int qb = blockIdx.x, h = blockIdx.y, kvh = h >> 2;
    const int tid = threadIdx.x, lane = tid & 31, wid = tid >> 5;
    const int wm = wid & 3, wn = wid >> 2;

    #pragma unroll
    for (int i = 0; i < 4; i++) {
        int idx = tid + i * 256;
        int row = idx >> 4, c = idx & 15;
        size_t go = (size_t)(qb * 64 + row) * QKV_N + h * HD + c * 8;
        uint32_t so = (uint32_t)(row * FROW + c * 16);
        CP_ASYNC16(sb + FS_Q  + so, qh_g + go);
        CP_ASYNC16(sb + FS_QL + so, ql_g + go);
    }
    if (tid < 64) { m_run[tid] = -INFINITY; l_run[tid] = 0.f; }
    CP_COMMIT();

    auto stageKV = [&](int b, int kb) {
        #pragma unroll
        for (int i = 0; i < 4; i++) {
            int idx = tid + i * 256;
            int row = idx >> 4, c = idx & 15;
            size_t gk = (size_t)(kb * 64 + row) * QKV_N + KOFF + kvh * HD + c * 8;
            size_t gv = (size_t)(kb * 64 + row) * QKV_N + VOFF + kvh * HD + c * 8;
            uint32_t so = (uint32_t)(row * FROW + c * 16);
            CP_ASYNC16(sb + FS_KH(b) + so, qh_g + gk);
            CP_ASYNC16(sb + FS_KL(b) + so, ql_g + gk);
            CP_ASYNC16(sb + FS_V(b)  + so, qh_g + gv);
        }
    };

    stageKV(0, 0);
    CP_COMMIT();

    float oacc[16][4];
    #pragma unroll
    for (int g = 0; g < 16; g++)
        #pragma unroll
        for (int q = 0; q < 4; q++) oacc[g][q] = 0.f;

    const int r0g = wm * 16 + (lane >> 2);
    const int r1g = r0g + 8;

    const uint32_t qaddr = sb + FS_Q
        + (uint32_t)(wm * 16 + (lane & 15)) * FROW + (uint32_t)((lane >> 4) * 8) * 2;
    const uint32_t krel = (uint32_t)(wn * 32 + (lane >> 4) * 8 + (lane & 7)) * FROW
        + (uint32_t)(((lane >> 3) & 1) * 8) * 2;
    const uint32_t vrel = (uint32_t)(wn * 32 + ((lane >> 3) & 1) * 8 + (lane & 7)) * FROW
        + (uint32_t)((lane >> 4) * 8) * 2;

    for (int kb = 0; kb <= qb; kb++) {
        if (kb < qb) { stageKV((kb + 1) & 1, kb + 1); CP_COMMIT(); CP_WAIT(1); }
        else         { CP_WAIT(0); }
        __syncthreads();

        const int buf = kb & 1;
        const uint32_t kaddr = sb + FS_KH(buf) + krel;
        const uint32_t vaddr = sb + FS_V(buf) + vrel;

        float sacc[4][4];
        #pragma unroll
        for (int nb = 0; nb < 4; nb++)
            #pragma unroll
            for (int q = 0; q < 4; q++) sacc[nb][q] = 0.f;

        #pragma unroll
        for (int d16 = 0; d16 < 8; d16++) {
            uint32_t qhf[4], qlf[4], kh[2][4], kl[2][4];
            LDSM_X4(qhf[0], qhf[1], qhf[2], qhf[3], qaddr + d16 * 32);
            LDSM_X4(qlf[0], qlf[1], qlf[2], qlf[3], qaddr + d16 * 32 + (FS_QL - FS_Q));
            LDSM_X4(kh[0][0], kh[0][1], kh[0][2], kh[0][3], kaddr + d16 * 32);
            LDSM_X4(kh[1][0], kh[1][1], kh[1][2], kh[1][3], kaddr + d16 * 32 + 16 * FROW);
            LDSM_X4(kl[0][0], kl[0][1], kl[0][2], kl[0][3], kaddr + d16 * 32 + 17408);
            LDSM_X4(kl[1][0], kl[1][1], kl[1][2], kl[1][3], kaddr + d16 * 32 + 17408 + 16 * FROW);
            #pragma unroll
            for (int p = 0; p < 2; p++) {
                MMA16816H(sacc[2 * p],     qhf, (&kh[p][0]));
                MMA16816H(sacc[2 * p + 1], qhf, (&kh[p][2]));
                MMA16816H(sacc[2 * p],     qhf, (&kl[p][0]));
                MMA16816H(sacc[2 * p + 1], qhf, (&kl[p][2]));
                MMA16816H(sacc[2 * p],     qlf, (&kh[p][0]));
                MMA16816H(sacc[2 * p + 1], qlf, (&kh[p][2]));
            }
        }

        if (kb == qb) {
            const int rr0 = wm * 16 + (lane >> 2), rr1 = rr0 + 8;
            #pragma unroll
            for (int nb = 0; nb < 4; nb++) {
                int c = wn * 32 + nb * 8 + (lane & 3) * 2;
                if (c     > rr0) sacc[nb][0] = -1e30f;
                if (c + 1 > rr0) sacc[nb][1] = -1e30f;
                if (c     > rr1) sacc[nb][2] = -1e30f;
                if (c + 1 > rr1) sacc[nb][3] = -1e30f;
            }
        }

        float mx0 = -INFINITY, mx1 = -INFINITY;
        #pragma unroll
        for (int nb = 0; nb < 4; nb++) {
            mx0 = fmaxf(mx0, fmaxf(sacc[nb][0], sacc[nb][1]));
            mx1 = fmaxf(mx1, fmaxf(sacc[nb][2], sacc[nb][3]));
        }
        mx0 = fmaxf(mx0, __shfl_xor_sync(0xffffffffu, mx0, 1));
        mx0 = fmaxf(mx0, __shfl_xor_sync(0xffffffffu, mx0, 2));
        mx1 = fmaxf(mx1, __shfl_xor_sync(0xffffffffu, mx1, 1));
        mx1 = fmaxf(mx1, __shfl_xor_sync(0xffffffffu, mx1, 2));
        if ((lane & 3) == 0) {
            m_half[wn * 64 + r0g] = mx0;
            m_half[wn * 64 + r1g] = mx1;
        }
        __syncthreads();

        const float mo0 = m_run[r0g], mo1 = m_run[r1g];
        const float mn0 = fmaxf(mo0, fmaxf(m_half[r0g], m_half[64 + r0g]));
        const float mn1 = fmaxf(mo1, fmaxf(m_half[r1g], m_half[64 + r1g]));
        const float al0 = __expf(mo0 - mn0), al1 = __expf(mo1 - mn1);

        float ls0 = 0.f, ls1 = 0.f;
        #pragma unroll
        for (int nb = 0; nb < 4; nb++) {
            sacc[nb][0] = __expf(sacc[nb][0] - mn0);
            sacc[nb][1] = __expf(sacc[nb][1] - mn0);
            sacc[nb][2] = __expf(sacc[nb][2] - mn1);
            sacc[nb][3] = __expf(sacc[nb][3] - mn1);
            ls0 += sacc[nb][0] + sacc[nb][1];
            ls1 += sacc[nb][2] + sacc[nb][3];
        }
        ls0 += __shfl_xor_sync(0xffffffffu, ls0, 1);
        ls0 += __shfl_xor_sync(0xffffffffu, ls0, 2);
        ls1 += __shfl_xor_sync(0xffffffffu, ls1, 1);
        ls1 += __shfl_xor_sync(0xffffffffu, ls1, 2);
        if ((lane & 3) == 0) {
            l_half[wn * 64 + r0g] = ls0;
            l_half[wn * 64 + r1g] = ls1;
        }
        __syncthreads();
        if (wn == 0 && (lane & 3) == 0) {
            m_run[r0g] = mn0;
            m_run[r1g] = mn1;
            l_run[r0g] = l_run[r0g] * al0 + l_half[r0g] + l_half[64 + r0g];
            l_run[r1g] = l_run[r1g] * al1 + l_half[r1g] + l_half[64 + r1g];
        }

        #pragma unroll
        for (int g = 0; g < 16; g++) {
            oacc[g][0] *= al0; oacc[g][1] *= al0;
            oacc[g][2] *= al1; oacc[g][3] *= al1;
        }

        #pragma unroll
        for (int t = 0; t < 2; t++) {
            uint32_t a[4];
            a[0] = pack_f16(sacc[2 * t][0],     sacc[2 * t][1]);
            a[1] = pack_f16(sacc[2 * t][2],     sacc[2 * t][3]);
            a[2] = pack_f16(sacc[2 * t + 1][0], sacc[2 * t + 1][1]);
            a[3] = pack_f16(sacc[2 * t + 1][2], sacc[2 * t + 1][3]);
            #pragma unroll
            for (int g = 0; g < 8; g++) {
                uint32_t v[4];
                LDSM_X4_T(v[0], v[1], v[2], v[3], vaddr + t * 16 * FROW + g * 32);
                MMA16816H(oacc[2 * g],     a, (&v[0]));
                MMA16816H(oacc[2 * g + 1], a, (&v[2]));
            }
        }
    }

    __syncthreads();
    float* Os = (float*)(sm + FS_KH(0));
    if (wn == 0) {
        #pragma unroll
        for (int g = 0; g < 16; g++) {
            int c = g * 8 + (lane & 3) * 2;
            Os[r0g * OSS + c]     = oacc[g][0];
            Os[r0g * OSS + c + 1] = oacc[g][1];
            Os[r1g * OSS + c]     = oacc[g][2];
            Os[r1g * OSS + c + 1] = oacc[g][3];
        }
    }
    __syncthreads();
    if (wn == 1) {
        const float inv0 = 1.f / l_run[r0g];
        const float inv1 = 1.f / l_run[r1g];
        #pragma unroll
        for (int g = 0; g < 16; g++) {
            int c = g * 8 + (lane & 3) * 2;
            float v0 = (Os[r0g * OSS + c]     + oacc[g][0]) * inv0;
            float v1 = (Os[r0g * OSS + c + 1] + oacc[g][1]) * inv0;
            float v2 = (Os[r1g * OSS + c]     + oacc[g][2]) * inv1;
            float v3 = (Os[r1g * OSS + c + 1] + oacc[g][3]) * inv1;
            size_t o0 = (size_t)(qb * 64 + r0g) * DIM + h * HD + c;
            size_t o1 = (size_t)(qb * 64 + r1g) * DIM + h * HD + c;
            *(uint32_t*)(oh + o0) = pack_f16(v0, v1);
            *(uint32_t*)(oh + o1) = pack_f16(v2, v3);
        }
    }
}

// ---------------------------------------------------------------------------
// Launch
// ---------------------------------------------------------------------------
extern "C" void kernel_launch(void* const* d_in, const int* in_sizes, int n_in,
                              void* d_out, int out_size)
{
    const float* x    = (const float*)d_in[0];
    const float* fc   = (const float*)d_in[1];
    const float* wqkv = (const float*)d_in[2];
    const float* wo   = (const float*)d_in[3];
    float* out = (float*)d_out;

    float* qkv = nullptr;
    __half *xh, *wqh, *woh, *ah, *qkvh, *qkvl;
    cudaGetSymbolAddress((void**)&qkv,  g_qkv);
    cudaGetSymbolAddress((void**)&xh,   g_xh);
    cudaGetSymbolAddress((void**)&wqh,  g_wqh);
    cudaGetSymbolAddress((void**)&woh,  g_woh);
    cudaGetSymbolAddress((void**)&ah,   g_ah);
    cudaGetSymbolAddress((void**)&qkvh, g_qkvh);
    cudaGetSymbolAddress((void**)&qkvl, g_qkvl);

    static bool attr_set = false;
    if (!attr_set) {
        cudaFuncSetAttribute(gemm_hmma1, cudaFuncAttributeMaxDynamicSharedMemorySize, GSM1_TOTAL);
        cudaFuncSetAttribute(flash_hmma, cudaFuncAttributeMaxDynamicSharedMemorySize, FS_TOTAL);
        attr_set = true;
    }

    // 0) convert fp32 inputs -> fp16
    {
        int n4;
        n4 = SEQ * DIM / 4;
        conv_f32h<<<(n4 + 255) / 256, 256>>>((const float4*)x, (uint2*)xh, n4);
        n4 = QKV_N * DIM / 4;
        conv_f32h<<<(n4 + 255) / 256, 256>>>((const float4*)wqkv, (uint2*)wqh, n4);
        n4 = DIM * DIM / 4;
        conv_f32h<<<(n4 + 255) / 256, 256>>>((const float4*)wo, (uint2*)woh, n4);
    }

    // 1) qkv = xh @ wqh^T  (1-pass fp16)
    gemm_hmma1<<<dim3(QKV_N / TBN, SEQ / TBM), 256, GSM1_TOTAL>>>(xh, wqh, qkv, QKV_N, DIM);

    // 2) fused RoPE + split qkv -> fp16 hi/lo (Q scaled; V hi only)
    {
        int n4 = SEQ * QKV_N / 4;
        rope_split<<<(n4 + 255) / 256, 256>>>((const float4*)qkv, fc, (uint2*)qkvh, (uint2*)qkvl);
    }

    // 3) HMMA flash attention (3-pass S, fp16 PV; writes fp16 attn)
    flash_hmma<<<dim3(SEQ / 64, NH), 256, FS_TOTAL>>>(qkvh, qkvl, ah);

    // 4) out = ah @ woh^T  (1-pass fp16)
    gemm_hmma1<<<dim3(DIM / TBN, SEQ / TBM), 256, GSM1_TOTAL>>>(ah, woh, out, DIM, DIM);
}

// round 17
// speedup vs baseline: 2.2586x; 1.1297x over previous
#include <cuda_runtime.h>
#include <cuda_bf16.h>
#include <cuda_fp16.h>
#include <math.h>
#include <stdint.h>

// Problem constants
#define SEQ   2048
#define DIM   4096
#define NH    32
#define NKV   8
#define HD    128
#define QKV_N 6144
#define KOFF  4096
#define VOFF  5120

// Scratch (__device__ globals), fp16 bits
__device__ float g_qkv[SEQ * QKV_N];
__device__ __half g_xh[SEQ * DIM];
__device__ __half g_wqh[QKV_N * DIM];
__device__ __half g_woh[DIM * DIM];
__device__ __half g_ah[SEQ * DIM];
__device__ __half g_qkvh[SEQ * QKV_N], g_qkvl[SEQ * QKV_N];

// ===========================================================================
// Helpers
// ===========================================================================
__device__ __forceinline__ uint32_t smem_u32(const void* p) {
    uint32_t a;
    asm("{ .reg .u64 t; cvta.to.shared.u64 t, %1; cvt.u32.u64 %0, t; }"
        : "=r"(a) : "l"(p));
    return a;
}

__device__ __forceinline__ uint32_t pack_f16(float f0, float f1) {
    uint32_t r;
    asm("cvt.rn.f16x2.f32 %0, %1, %2;" : "=r"(r) : "f"(f1), "f"(f0));
    return r;
}

__device__ __forceinline__ void split2h(float f0, float f1, uint32_t& hi, uint32_t& lo) {
    hi = pack_f16(f0, f1);
    __half2 h = *reinterpret_cast<__half2*>(&hi);
    float h0 = __low2float(h), h1 = __high2float(h);
    lo = pack_f16(f0 - h0, f1 - h1);
}

#define CP_ASYNC16(dst, src) \
    asm volatile("cp.async.cg.shared.global [%0], [%1], 16;" :: "r"(dst), "l"(src) : "memory")
#define CP_COMMIT() asm volatile("cp.async.commit_group;" ::: "memory")
#define CP_WAIT(n)  asm volatile("cp.async.wait_group %0;" :: "n"(n) : "memory")

#define LDSM_X4(r0, r1, r2, r3, addr) \
    asm volatile("ldmatrix.sync.aligned.m8n8.x4.shared.b16 {%0,%1,%2,%3}, [%4];" \
                 : "=r"(r0), "=r"(r1), "=r"(r2), "=r"(r3) : "r"(addr))
#define LDSM_X4_T(r0, r1, r2, r3, addr) \
    asm volatile("ldmatrix.sync.aligned.m8n8.x4.trans.shared.b16 {%0,%1,%2,%3}, [%4];" \
                 : "=r"(r0), "=r"(r1), "=r"(r2), "=r"(r3) : "r"(addr))

#define MMA16816H(c, a, b) \
    asm volatile("mma.sync.aligned.m16n8k16.row.col.f32.f16.f16.f32 " \
                 "{%0,%1,%2,%3}, {%4,%5,%6,%7}, {%8,%9}, {%0,%1,%2,%3};" \
                 : "+f"((c)[0]), "+f"((c)[1]), "+f"((c)[2]), "+f"((c)[3]) \
                 : "r"((a)[0]), "r"((a)[1]), "r"((a)[2]), "r"((a)[3]), \
                   "r"((b)[0]), "r"((b)[1]))

// ===========================================================================
// fp32 -> fp16 (round-to-nearest)
// ===========================================================================
__global__ __launch_bounds__(256)
void conv_f32h(const float4* __restrict__ in, uint2* __restrict__ hi, int n4)
{
    int i = blockIdx.x * blockDim.x + threadIdx.x;
    if (i >= n4) return;
    float4 v = in[i];
    hi[i] = make_uint2(pack_f16(v.x, v.y), pack_f16(v.z, v.w));
}

// Fused RoPE + split: Q (rope+scale) / K (rope) -> fp16 hi/lo; V -> fp16 hi only.
__global__ __launch_bounds__(256)
void rope_split(const float4* __restrict__ in, const float* __restrict__ fc,
                uint2* __restrict__ hi, uint2* __restrict__ lo)
{
    int i = blockIdx.x * blockDim.x + threadIdx.x;
    const int n4 = SEQ * QKV_N / 4;
    if (i >= n4) return;
    int col = (i * 4) % QKV_N;
    int s   = (i * 4) / QKV_N;
    float4 v = in[i];
    if (col < VOFF) {
        int d = col & 127;
        const float* f = fc + s * HD + d;
        float c0 = f[0], s0 = f[1], c1 = f[2], s1 = f[3];
        float r0 = v.x * c0 - v.y * s0, r1 = v.x * s0 + v.y * c0;
        float r2 = v.z * c1 - v.w * s1, r3 = v.z * s1 + v.w * c1;
        float sc = (col < KOFF) ? 0.08838834764831845f : 1.0f;
        uint32_t h01, l01, h23, l23;
        split2h(r0 * sc, r1 * sc, h01, l01);
        split2h(r2 * sc, r3 * sc, h23, l23);
        hi[i] = make_uint2(h01, h23);
        lo[i] = make_uint2(l01, l23);
    } else {
        hi[i] = make_uint2(pack_f16(v.x, v.y), pack_f16(v.z, v.w));
    }
}

// ===========================================================================
// 1-pass fp16 GEMM (NT): C = Ah * Bh^T. 256 thr, 8 warps (4Mx2N),
// warp tile 32x64, BK=64, 3-stage cp.async pipeline, 2 CTAs/SM.
// ===========================================================================
#define TBM 128
#define TBN 128
#define TBK 64
#define SROW 144
#define SARR 18432
#define SSTG1 36864
#define NSTG1 3
#define GSM1_TOTAL (NSTG1 * SSTG1)   // 110592 -> 2 CTAs/SM

__global__ __launch_bounds__(256, 2)
void gemm_hmma1(const __half* __restrict__ Ah, const __half* __restrict__ Bh,
                float* __restrict__ C, int N, int K)
{
    extern __shared__ char sm[];
    const uint32_t sb = smem_u32(sm);
    const int tid = threadIdx.x, lane = tid & 31, wid = tid >> 5;
    const int wm = wid & 3, wn = wid >> 2;
    const int bx = blockIdx.x, by = blockIdx.y;

    const __half* Ahp = Ah + (size_t)(by * TBM) * K;
    const __half* Bhp = Bh + (size_t)(bx * TBN) * K;

    float acc[2][8][4];
    #pragma unroll
    for (int i = 0; i < 2; i++)
        #pragma unroll
        for (int j = 0; j < 8; j++)
            #pragma unroll
            for (int q = 0; q < 4; q++) acc[i][j][q] = 0.f;

    auto stage = [&](int s, int t) {
        const uint32_t sd = sb + s * SSTG1;
        #pragma unroll
        for (int i = 0; i < 4; i++) {
            int idx = tid + i * 256;
            int row = idx >> 3, c = idx & 7;
            size_t goff = (size_t)row * K + t * TBK + c * 8;
            uint32_t doff = row * SROW + c * 16;
            CP_ASYNC16(sd + doff,        Ahp + goff);
            CP_ASYNC16(sd + SARR + doff, Bhp + goff);
        }
    };

    uint32_t ah[2][2][4], bh[2][8][2];

    auto ldfrag = [&](int s, int ks, int buf) {
        const uint32_t sd = sb + s * SSTG1;
        #pragma unroll
        for (int mi = 0; mi < 2; mi++) {
            uint32_t addr = sd + (uint32_t)(wm * 32 + mi * 16 + (lane & 15)) * SROW
                          + (uint32_t)(ks * 16 + (lane >> 4) * 8) * 2;
            LDSM_X4(ah[buf][mi][0], ah[buf][mi][1], ah[buf][mi][2], ah[buf][mi][3], addr);
        }
        #pragma unroll
        for (int nj = 0; nj < 4; nj++) {
            int half_ = lane >> 4, r8 = (lane >> 3) & 1;
            uint32_t addr = sd + SARR
                          + (uint32_t)(wn * 64 + nj * 16 + half_ * 8 + (lane & 7)) * SROW
                          + (uint32_t)(ks * 16 + r8 * 8) * 2;
            LDSM_X4(bh[buf][2 * nj][0], bh[buf][2 * nj][1],
                    bh[buf][2 * nj + 1][0], bh[buf][2 * nj + 1][1], addr);
        }
    };

    auto mmastep = [&](int buf) {
        #pragma unroll
        for (int mi = 0; mi < 2; mi++)
            #pragma unroll
            for (int ni = 0; ni < 8; ni++)
                MMA16816H(acc[mi][ni], ah[buf][mi], bh[buf][ni]);
    };

    const int KT = K / TBK;
    stage(0, 0); CP_COMMIT();
    stage(1, 1); CP_COMMIT();

    int s = 0;
    for (int t = 0; t < KT; t++) {
        if (t + 2 < KT) {
            stage((s + 2) % NSTG1, t + 2);
            CP_COMMIT();
            CP_WAIT(2);
        } else {
            CP_WAIT(0);
        }
        __syncthreads();

        ldfrag(s, 0, 0);
        #pragma unroll
        for (int ks = 0; ks < 4; ks++) {
            const int cur = ks & 1;
            if (ks < 3) ldfrag(s, ks + 1, cur ^ 1);
            mmastep(cur);
        }
        __syncthreads();
        s = (s + 1) % NSTG1;
    }

    #pragma unroll
    for (int mi = 0; mi < 2; mi++) {
        #pragma unroll
        for (int ni = 0; ni < 8; ni++) {
            int r0 = by * TBM + wm * 32 + mi * 16 + (lane >> 2);
            int c0 = bx * TBN + wn * 64 + ni * 8 + (lane & 3) * 2;
            *(float2*)&C[(size_t)r0 * N + c0]       = make_float2(acc[mi][ni][0], acc[mi][ni][1]);
            *(float2*)&C[(size_t)(r0 + 8) * N + c0] = make_float2(acc[mi][ni][2], acc[mi][ni][3]);
        }
    }
}

// ===========================================================================
// HMMA flash attention (unchanged)
// ===========================================================================
#define FROW 272
#define FS_Q    1536
#define FS_QL   18944
#define FS_KH(b) (36352 + (b) * 34816)
#define FS_KL(b) (FS_KH(b) + 17408)
#define FS_V(b)  (105984 + (b) * 17408)
#define FS_TOTAL 140800
#define OSS 132

__global__ __launch_bounds__(256)
void flash_hmma(const __half* __restrict__ qh_g, const __half* __restrict__ ql_g,
                __half* __restrict__ oh)
{
    extern __shared__ char sm[];
    const uint32_t sb = smem_u32(sm);
    float* m_run  = (float*)(sm);
    float* l_run  = (float*)(sm + 256);
    float* m_half = (float*)(sm + 512);
    float* l_half = (float*)(sm + 1024);

    const int qb = blockIdx.x, h = blockIdx.y, kvh = h >> 2;
    const int tid = threadIdx.x, lane = tid & 31, wid = tid >> 5;
    const int wm = wid & 3, wn = wid >> 2;

    #pragma unroll
    for (int i = 0; i < 4; i++) {
        int idx = tid + i * 256;
        int row = idx >> 4, c = idx & 15;
        size_t go = (size_t)(qb * 64 + row) * QKV_N + h * HD + c * 8;
        uint32_t so = (uint32_t)(row * FROW + c * 16);
        CP_ASYNC16(sb + FS_Q  + so, qh_g + go);
        CP_ASYNC16(sb + FS_QL + so, ql_g + go);
    }
    if (tid < 64) { m_run[tid] = -INFINITY; l_run[tid] = 0.f; }
    CP_COMMIT();

    auto stageKV = [&](int b, int kb) {
        #pragma unroll
        for (int i = 0; i < 4; i++) {
            int idx = tid + i * 256;
            int row = idx >> 4, c = idx & 15;
            size_t gk = (size_t)(kb * 64 + row) * QKV_N + KOFF + kvh * HD + c * 8;
            size_t gv = (size_t)(kb * 64 + row) * QKV_N + VOFF + kvh * HD + c * 8;
            uint32_t so = (uint32_t)(row * FROW + c * 16);
            CP_ASYNC16(sb + FS_KH(b) + so, qh_g + gk);
            CP_ASYNC16(sb + FS_KL(b) + so, ql_g + gk);
            CP_ASYNC16(sb + FS_V(b)  + so, qh_g + gv);
        }
    };

    stageKV(0, 0);
    CP_COMMIT();

    float oacc[16][4];
    #pragma unroll
    for (int g = 0; g < 16; g++)
        #pragma unroll
        for (int q = 0; q < 4; q++) oacc[g][q] = 0.f;

    const int r0g = wm * 16 + (lane >> 2);
    const int r1g = r0g + 8;

    const uint32_t qaddr = sb + FS_Q
        + (uint32_t)(wm * 16 + (lane & 15)) * FROW + (uint32_t)((lane >> 4) * 8) * 2;
    const uint32_t krel = (uint32_t)(wn * 32 + (lane >> 4) * 8 + (lane & 7)) * FROW
        + (uint32_t)(((lane >> 3) & 1) * 8) * 2;
    const uint32_t vrel = (uint32_t)(wn * 32 + ((lane >> 3) & 1) * 8 + (lane & 7)) * FROW
        + (uint32_t)((lane >> 4) * 8) * 2;

    for (int kb = 0; kb <= qb; kb++) {
        if (kb < qb) { stageKV((kb + 1) & 1, kb + 1); CP_COMMIT(); CP_WAIT(1); }
        else         { CP_WAIT(0); }
        __syncthreads();

        const int buf = kb & 1;
        const uint32_t kaddr = sb + FS_KH(buf) + krel;
        const uint32_t vaddr = sb + FS_V(buf) + vrel;

        float sacc[4][4];
        #pragma unroll
        for (int nb = 0; nb < 4; nb++)
            #pragma unroll
            for (int q = 0; q < 4; q++) sacc[nb][q] = 0.f;

        #pragma unroll
        for (int d16 = 0; d16 < 8; d16++) {
            uint32_t qhf[4], qlf[4], kh[2][4], kl[2][4];
            LDSM_X4(qhf[0], qhf[1], qhf[2], qhf[3], qaddr + d16 * 32);
            LDSM_X4(qlf[0], qlf[1], qlf[2], qlf[3], qaddr + d16 * 32 + (FS_QL - FS_Q));
            LDSM_X4(kh[0][0], kh[0][1], kh[0][2], kh[0][3], kaddr + d16 * 32);
            LDSM_X4(kh[1][0], kh[1][1], kh[1][2], kh[1][3], kaddr + d16 * 32 + 16 * FROW);
            LDSM_X4(kl[0][0], kl[0][1], kl[0][2], kl[0][3], kaddr + d16 * 32 + 17408);
            LDSM_X4(kl[1][0], kl[1][1], kl[1][2], kl[1][3], kaddr + d16 * 32 + 17408 + 16 * FROW);
            #pragma unroll
            for (int p = 0; p < 2; p++) {
                MMA16816H(sacc[2 * p],     qhf, (&kh[p][0]));
                MMA16816H(sacc[2 * p + 1], qhf, (&kh[p][2]));
                MMA16816H(sacc[2 * p],     qhf, (&kl[p][0]));
                MMA16816H(sacc[2 * p + 1], qhf, (&kl[p][2]));
                MMA16816H(sacc[2 * p],     qlf, (&kh[p][0]));
                MMA16816H(sacc[2 * p + 1], qlf, (&kh[p][2]));
            }
        }

        if (kb == qb) {
            const int rr0 = wm * 16 + (lane >> 2), rr1 = rr0 + 8;
            #pragma unroll
            for (int nb = 0; nb < 4; nb++) {
                int c = wn * 32 + nb * 8 + (lane & 3) * 2;
                if (c     > rr0) sacc[nb][0] = -1e30f;
                if (c + 1 > rr0) sacc[nb][1] = -1e30f;
                if (c     > rr1) sacc[nb][2] = -1e30f;
                if (c + 1 > rr1) sacc[nb][3] = -1e30f;
            }
        }

        float mx0 = -INFINITY, mx1 = -INFINITY;
        #pragma unroll
        for (int nb = 0; nb < 4; nb++) {
            mx0 = fmaxf(mx0, fmaxf(sacc[nb][0], sacc[nb][1]));
            mx1 = fmaxf(mx1, fmaxf(sacc[nb][2], sacc[nb][3]));
        }
        mx0 = fmaxf(mx0, __shfl_xor_sync(0xffffffffu, mx0, 1));
        mx0 = fmaxf(mx0, __shfl_xor_sync(0xffffffffu, mx0, 2));
        mx1 = fmaxf(mx1, __shfl_xor_sync(0xffffffffu, mx1, 1));
        mx1 = fmaxf(mx1, __shfl_xor_sync(0xffffffffu, mx1, 2));
        if ((lane & 3) == 0) {
            m_half[wn * 64 + r0g] = mx0;
            m_half[wn * 64 + r1g] = mx1;
        }
        __syncthreads();

        const float mo0 = m_run[r0g], mo1 = m_run[r1g];
        const float mn0 = fmaxf(mo0, fmaxf(m_half[r0g], m_half[64 + r0g]));
        const float mn1 = fmaxf(mo1, fmaxf(m_half[r1g], m_half[64 + r1g]));
        const float al0 = __expf(mo0 - mn0), al1 = __expf(mo1 - mn1);

        float ls0 = 0.f, ls1 = 0.f;
        #pragma unroll
        for (int nb = 0; nb < 4; nb++) {
            sacc[nb][0] = __expf(sacc[nb][0] - mn0);
            sacc[nb][1] = __expf(sacc[nb][1] - mn0);
            sacc[nb][2] = __expf(sacc[nb][2] - mn1);
            sacc[nb][3] = __expf(sacc[nb][3] - mn1);
            ls0 += sacc[nb][0] + sacc[nb][1];
            ls1 += sacc[nb][2] + sacc[nb][3];
        }
        ls0 += __shfl_xor_sync(0xffffffffu, ls0, 1);
        ls0 += __shfl_xor_sync(0xffffffffu, ls0, 2);
        ls1 += __shfl_xor_sync(0xffffffffu, ls1, 1);
        ls1 += __shfl_xor_sync(0xffffffffu, ls1, 2);
        if ((lane & 3) == 0) {
            l_half[wn * 64 + r0g] = ls0;
            l_half[wn * 64 + r1g] = ls1;
        }
        __syncthreads();
        if (wn == 0 && (lane & 3) == 0) {
            m_run[r0g] = mn0;
            m_run[r1g] = mn1;
            l_run[r0g] = l_run[r0g] * al0 + l_half[r0g] + l_half[64 + r0g];
            l_run[r1g] = l_run[r1g] * al1 + l_half[r1g] + l_half[64 + r1g];
        }

        #pragma unroll
        for (int g = 0; g < 16; g++) {
            oacc[g][0] *= al0; oacc[g][1] *= al0;
            oacc[g][2] *= al1; oacc[g][3] *= al1;
        }

        #pragma unroll
        for (int t = 0; t < 2; t++) {
            uint32_t a[4];
            a[0] = pack_f16(sacc[2 * t][0],     sacc[2 * t][1]);
            a[1] = pack_f16(sacc[2 * t][2],     sacc[2 * t][3]);
            a[2] = pack_f16(sacc[2 * t + 1][0], sacc[2 * t + 1][1]);
            a[3] = pack_f16(sacc[2 * t + 1][2], sacc[2 * t + 1][3]);
            #pragma unroll
            for (int g = 0; g < 8; g++) {
                uint32_t v[4];
                LDSM_X4_T(v[0], v[1], v[2], v[3], vaddr + t * 16 * FROW + g * 32);
                MMA16816H(oacc[2 * g],     a, (&v[0]));
                MMA16816H(oacc[2 * g + 1], a, (&v[2]));
            }
        }
    }

    __syncthreads();
    float* Os = (float*)(sm + FS_KH(0));
    if (wn == 0) {
        #pragma unroll
        for (int g = 0; g < 16; g++) {
            int c = g * 8 + (lane & 3) * 2;
            Os[r0g * OSS + c]     = oacc[g][0];
            Os[r0g * OSS + c + 1] = oacc[g][1];
            Os[r1g * OSS + c]     = oacc[g][2];
            Os[r1g * OSS + c + 1] = oacc[g][3];
        }
    }
    __syncthreads();
    if (wn == 1) {
        const float inv0 = 1.f / l_run[r0g];
        const float inv1 = 1.f / l_run[r1g];
        #pragma unroll
        for (int g = 0; g < 16; g++) {
            int c = g * 8 + (lane & 3) * 2;
            float v0 = (Os[r0g * OSS + c]     + oacc[g][0]) * inv0;
            float v1 = (Os[r0g * OSS + c + 1] + oacc[g][1]) * inv0;
            float v2 = (Os[r1g * OSS + c]     + oacc[g][2]) * inv1;
            float v3 = (Os[r1g * OSS + c + 1] + oacc[g][3]) * inv1;
            size_t o0 = (size_t)(qb * 64 + r0g) * DIM + h * HD + c;
            size_t o1 = (size_t)(qb * 64 + r1g) * DIM + h * HD + c;
            *(uint32_t*)(oh + o0) = pack_f16(v0, v1);
            *(uint32_t*)(oh + o1) = pack_f16(v2, v3);
        }
    }
}

// ---------------------------------------------------------------------------
// Launch
// ---------------------------------------------------------------------------
extern "C" void kernel_launch(void* const* d_in, const int* in_sizes, int n_in,
                              void* d_out, int out_size)
{
    const float* x    = (const float*)d_in[0];
    const float* fc   = (const float*)d_in[1];
    const float* wqkv = (const float*)d_in[2];
    const float* wo   = (const float*)d_in[3];
    float* out = (float*)d_out;

    float* qkv = nullptr;
    __half *xh, *wqh, *woh, *ah, *qkvh, *qkvl;
    cudaGetSymbolAddress((void**)&qkv,  g_qkv);
    cudaGetSymbolAddress((void**)&xh,   g_xh);
    cudaGetSymbolAddress((void**)&wqh,  g_wqh);
    cudaGetSymbolAddress((void**)&woh,  g_woh);
    cudaGetSymbolAddress((void**)&ah,   g_ah);
    cudaGetSymbolAddress((void**)&qkvh, g_qkvh);
    cudaGetSymbolAddress((void**)&qkvl, g_qkvl);

    static bool attr_set = false;
    if (!attr_set) {
        cudaFuncSetAttribute(gemm_hmma1, cudaFuncAttributeMaxDynamicSharedMemorySize, GSM1_TOTAL);
        cudaFuncSetAttribute(flash_hmma, cudaFuncAttributeMaxDynamicSharedMemorySize, FS_TOTAL);
        attr_set = true;
    }

    // 0) convert fp32 inputs -> fp16
    {
        int n4;
        n4 = SEQ * DIM / 4;
        conv_f32h<<<(n4 + 255) / 256, 256>>>((const float4*)x, (uint2*)xh, n4);
        n4 = QKV_N * DIM / 4;
        conv_f32h<<<(n4 + 255) / 256, 256>>>((const float4*)wqkv, (uint2*)wqh, n4);
        n4 = DIM * DIM / 4;
        conv_f32h<<<(n4 + 255) / 256, 256>>>((const float4*)wo, (uint2*)woh, n4);
    }

    // 1) qkv = xh @ wqh^T  (1-pass fp16)
    gemm_hmma1<<<dim3(QKV_N / TBN, SEQ / TBM), 256, GSM1_TOTAL>>>(xh, wqh, qkv, QKV_N, DIM);

    // 2) fused RoPE + split qkv -> fp16 hi/lo (Q scaled; V hi only)
    {
        int n4 = SEQ * QKV_N / 4;
        rope_split<<<(n4 + 255) / 256, 256>>>((const float4*)qkv, fc, (uint2*)qkvh, (uint2*)qkvl);
    }

    // 3) HMMA flash attention (3-pass S, fp16 PV; writes fp16 attn)
    flash_hmma<<<dim3(SEQ / 64, NH), 256, FS_TOTAL>>>(qkvh, qkvl, ah);

    // 4) out = ah @ woh^T  (1-pass fp16)
    gemm_hmma1<<<dim3(DIM / TBN, SEQ / TBM), 256, GSM1_TOTAL>>>(ah, woh, out, DIM, DIM);
}